// round 1
// baseline (speedup 1.0000x reference)
#include <cuda_runtime.h>
#include <math.h>

// Problem constants
#define BB 8
#define NN 16384
#define SSZ 2048
#define C1V 128
#define C2V 256
#define CF 384
#define MM (BB*NN)      /* 131072 rows */
#define OO 256          /* output channels per layer */

// -------- scratch (static device globals; no allocation allowed) --------
__device__ float g_fused[(long long)MM * CF];   // 192 MB: concat(points1, interpolated)
__device__ float g_h[(long long)MM * OO];       // 128 MB: layer-1 pre-BN activations
__device__ float g_part[512 * 512];             // per-block partial sums/sumsq
__device__ float g_s1[OO], g_t1[OO], g_s2[OO], g_t2[OO]; // BN scale/shift

// -------- packed f32x2 helpers (Blackwell packed FP32 pipe) --------
__device__ __forceinline__ unsigned long long dup2(float x) {
    unsigned long long r;
    asm("mov.b64 %0, {%1, %1};" : "=l"(r) : "f"(x));
    return r;
}
__device__ __forceinline__ unsigned long long ffma2(unsigned long long a,
                                                    unsigned long long b,
                                                    unsigned long long c) {
    unsigned long long d;
    asm("fma.rn.f32x2 %0, %1, %2, %3;" : "=l"(d) : "l"(a), "l"(b), "l"(c));
    return d;
}
__device__ __forceinline__ float2 unpack2(unsigned long long v) {
    float2 r;
    asm("mov.b64 {%0, %1}, %2;" : "=f"(r.x), "=f"(r.y) : "l"(v));
    return r;
}

// ======================================================================
// Kernel 1: 3-NN search + inverse-distance interpolation + concat
// grid (NN/256, BB), 256 threads. xyz2 of one batch cached in smem (24KB).
// ======================================================================
__global__ void knn_interp_kernel(const float* __restrict__ xyz1,
                                  const float* __restrict__ xyz2,
                                  const float* __restrict__ points1,
                                  const float* __restrict__ points2) {
    __shared__ float sx[SSZ], sy[SSZ], sz[SSZ];
    __shared__ int   sidx[256][3];
    __shared__ float swt[256][3];

    const int tid = threadIdx.x;
    const int b   = blockIdx.y;
    const int n0  = blockIdx.x * 256;

    // load xyz2[b] (coalesced), scatter to SoA
    const float* x2 = xyz2 + (long long)b * SSZ * 3;
    for (int i = tid; i < SSZ * 3; i += 256) {
        float v = x2[i];
        int s = i / 3, d = i - s * 3;
        if (d == 0) sx[s] = v; else if (d == 1) sy[s] = v; else sz[s] = v;
    }
    __syncthreads();

    // each thread: one query point, scan all S candidates, keep top-3 smallest d2
    const int n = n0 + tid;
    const float* p = xyz1 + ((long long)b * NN + n) * 3;
    const float px = p[0], py = p[1], pz = p[2];
    float b0 = 3.4e38f, b1 = 3.4e38f, b2 = 3.4e38f;
    int   j0 = 0, j1 = 0, j2 = 0;
    #pragma unroll 4
    for (int s = 0; s < SSZ; ++s) {
        float dx = px - sx[s], dy = py - sy[s], dz = pz - sz[s];
        float d = dx*dx + dy*dy + dz*dz;
        if (d < b2) {
            if (d < b1) {
                b2 = b1; j2 = j1;
                if (d < b0) { b1 = b0; j1 = j0; b0 = d; j0 = s; }
                else        { b1 = d;  j1 = s; }
            } else { b2 = d; j2 = s; }
        }
    }
    // weights: 1/(sqrt(d)+eps), normalized
    float r0 = 1.f / (sqrtf(b0) + 1e-8f);
    float r1 = 1.f / (sqrtf(b1) + 1e-8f);
    float r2 = 1.f / (sqrtf(b2) + 1e-8f);
    float rs = 1.f / (r0 + r1 + r2);
    sidx[tid][0] = j0; sidx[tid][1] = j1; sidx[tid][2] = j2;
    swt[tid][0] = r0 * rs; swt[tid][1] = r1 * rs; swt[tid][2] = r2 * rs;
    __syncthreads();

    // Phase B: coalesced gather of neighbor features (C2=256 ch) -> fused[:,128:384]
    const float4* p2 = (const float4*)(points2 + (long long)b * SSZ * C2V);
    float* fo = g_fused + ((long long)b * NN + n0) * CF;
    const int lp = tid >> 6;       // 4 points per iteration
    const int c4 = tid & 63;       // float4 channel index (0..63)
    for (int pb = 0; pb < 256; pb += 4) {
        const int pp = pb + lp;
        const int i0 = sidx[pp][0], i1 = sidx[pp][1], i2 = sidx[pp][2];
        const float w0 = swt[pp][0], w1 = swt[pp][1], w2 = swt[pp][2];
        float4 v0 = p2[(long long)i0 * 64 + c4];
        float4 v1 = p2[(long long)i1 * 64 + c4];
        float4 v2 = p2[(long long)i2 * 64 + c4];
        float4 r;
        r.x = w0*v0.x + w1*v1.x + w2*v2.x;
        r.y = w0*v0.y + w1*v1.y + w2*v2.y;
        r.z = w0*v0.z + w1*v1.z + w2*v2.z;
        r.w = w0*v0.w + w1*v1.w + w2*v2.w;
        *(float4*)(fo + (long long)pp * CF + C1V + c4 * 4) = r;
    }

    // copy points1 -> fused[:,0:128]
    const float4* p1 = (const float4*)(points1 + ((long long)b * NN + n0) * C1V);
    for (int i = tid; i < 256 * 32; i += 256) {
        const int pp = i >> 5, cc = i & 31;
        *(float4*)(fo + (long long)pp * CF + cc * 4) = p1[i];
    }
}

// ======================================================================
// GEMM: C[M,256] = A[M,K] @ W[256,K]^T + bias, optional BN+ReLU on A load.
// 128x128 tile, BK=8, 256 threads, 8x8 per thread via packed f32x2 FFMA.
// ======================================================================
template<int K, bool BN>
__device__ __forceinline__ void gemm_body(const float* __restrict__ A,
                                          const float* __restrict__ W,
                                          const float* __restrict__ bias,
                                          float* __restrict__ C,
                                          const float* __restrict__ bnS,
                                          const float* __restrict__ bnT) {
    __shared__ float As[8][132];
    __shared__ float Ws[8][132];
    __shared__ float sS[CF], sT[CF];

    const int tid = threadIdx.x;
    const int m0 = blockIdx.y << 7;
    const int o0 = blockIdx.x << 7;

    if (BN) {
        for (int i = tid; i < K; i += 256) { sS[i] = bnS[i]; sT[i] = bnT[i]; }
    }
    __syncthreads();

    const int lrow = tid >> 1;
    const int lk   = (tid & 1) << 2;
    const float* Ag = A + (long long)(m0 + lrow) * K + lk;
    const float* Wg = W + (long long)(o0 + lrow) * K + lk;
    const int ty = tid >> 4, tx = tid & 15;

    unsigned long long acc[4][8];
    #pragma unroll
    for (int q = 0; q < 4; q++)
        #pragma unroll
        for (int j = 0; j < 8; j++) acc[q][j] = 0ull;

    float4 av = *(const float4*)Ag;
    float4 wv = *(const float4*)Wg;
    if (BN) {
        av.x = fmaxf(fmaf(av.x, sS[lk+0], sT[lk+0]), 0.f);
        av.y = fmaxf(fmaf(av.y, sS[lk+1], sT[lk+1]), 0.f);
        av.z = fmaxf(fmaf(av.z, sS[lk+2], sT[lk+2]), 0.f);
        av.w = fmaxf(fmaf(av.w, sS[lk+3], sT[lk+3]), 0.f);
    }

    for (int kt = 0; kt < K; kt += 8) {
        __syncthreads();
        As[lk+0][lrow] = av.x; As[lk+1][lrow] = av.y;
        As[lk+2][lrow] = av.z; As[lk+3][lrow] = av.w;
        Ws[lk+0][lrow] = wv.x; Ws[lk+1][lrow] = wv.y;
        Ws[lk+2][lrow] = wv.z; Ws[lk+3][lrow] = wv.w;
        __syncthreads();

        float4 avn = make_float4(0.f,0.f,0.f,0.f);
        float4 wvn = make_float4(0.f,0.f,0.f,0.f);
        if (kt + 8 < K) {
            avn = *(const float4*)(Ag + kt + 8);
            wvn = *(const float4*)(Wg + kt + 8);
            if (BN) {
                const int c = kt + 8 + lk;
                avn.x = fmaxf(fmaf(avn.x, sS[c+0], sT[c+0]), 0.f);
                avn.y = fmaxf(fmaf(avn.y, sS[c+1], sT[c+1]), 0.f);
                avn.z = fmaxf(fmaf(avn.z, sS[c+2], sT[c+2]), 0.f);
                avn.w = fmaxf(fmaf(avn.w, sS[c+3], sT[c+3]), 0.f);
            }
        }

        #pragma unroll
        for (int kk = 0; kk < 8; kk++) {
            const unsigned long long* A64 = (const unsigned long long*)(&As[kk][0]);
            const unsigned long long a0 = A64[ty*4+0];
            const unsigned long long a1 = A64[ty*4+1];
            const unsigned long long a2 = A64[ty*4+2];
            const unsigned long long a3 = A64[ty*4+3];
            const float4* Wr = (const float4*)(&Ws[kk][0]);
            const float4 w0 = Wr[tx*2], w1 = Wr[tx*2+1];
            const unsigned long long d0 = dup2(w0.x), d1 = dup2(w0.y);
            const unsigned long long d2 = dup2(w0.z), d3 = dup2(w0.w);
            const unsigned long long d4 = dup2(w1.x), d5 = dup2(w1.y);
            const unsigned long long d6 = dup2(w1.z), d7 = dup2(w1.w);
            acc[0][0]=ffma2(a0,d0,acc[0][0]); acc[0][1]=ffma2(a0,d1,acc[0][1]);
            acc[0][2]=ffma2(a0,d2,acc[0][2]); acc[0][3]=ffma2(a0,d3,acc[0][3]);
            acc[0][4]=ffma2(a0,d4,acc[0][4]); acc[0][5]=ffma2(a0,d5,acc[0][5]);
            acc[0][6]=ffma2(a0,d6,acc[0][6]); acc[0][7]=ffma2(a0,d7,acc[0][7]);
            acc[1][0]=ffma2(a1,d0,acc[1][0]); acc[1][1]=ffma2(a1,d1,acc[1][1]);
            acc[1][2]=ffma2(a1,d2,acc[1][2]); acc[1][3]=ffma2(a1,d3,acc[1][3]);
            acc[1][4]=ffma2(a1,d4,acc[1][4]); acc[1][5]=ffma2(a1,d5,acc[1][5]);
            acc[1][6]=ffma2(a1,d6,acc[1][6]); acc[1][7]=ffma2(a1,d7,acc[1][7]);
            acc[2][0]=ffma2(a2,d0,acc[2][0]); acc[2][1]=ffma2(a2,d1,acc[2][1]);
            acc[2][2]=ffma2(a2,d2,acc[2][2]); acc[2][3]=ffma2(a2,d3,acc[2][3]);
            acc[2][4]=ffma2(a2,d4,acc[2][4]); acc[2][5]=ffma2(a2,d5,acc[2][5]);
            acc[2][6]=ffma2(a2,d6,acc[2][6]); acc[2][7]=ffma2(a2,d7,acc[2][7]);
            acc[3][0]=ffma2(a3,d0,acc[3][0]); acc[3][1]=ffma2(a3,d1,acc[3][1]);
            acc[3][2]=ffma2(a3,d2,acc[3][2]); acc[3][3]=ffma2(a3,d3,acc[3][3]);
            acc[3][4]=ffma2(a3,d4,acc[3][4]); acc[3][5]=ffma2(a3,d5,acc[3][5]);
            acc[3][6]=ffma2(a3,d6,acc[3][6]); acc[3][7]=ffma2(a3,d7,acc[3][7]);
        }
        av = avn; wv = wvn;
    }

    // epilogue: add bias, write 8x8 per thread
    const float4 bs0 = *(const float4*)(bias + o0 + tx*8);
    const float4 bs1 = *(const float4*)(bias + o0 + tx*8 + 4);
    #pragma unroll
    for (int q = 0; q < 4; q++) {
        float2 u0 = unpack2(acc[q][0]), u1 = unpack2(acc[q][1]);
        float2 u2 = unpack2(acc[q][2]), u3 = unpack2(acc[q][3]);
        float2 u4 = unpack2(acc[q][4]), u5 = unpack2(acc[q][5]);
        float2 u6 = unpack2(acc[q][6]), u7 = unpack2(acc[q][7]);
        float* cr = C + (long long)(m0 + ty*8 + 2*q) * OO + o0 + tx*8;
        float4 lo0 = make_float4(u0.x+bs0.x, u1.x+bs0.y, u2.x+bs0.z, u3.x+bs0.w);
        float4 lo1 = make_float4(u4.x+bs1.x, u5.x+bs1.y, u6.x+bs1.z, u7.x+bs1.w);
        *(float4*)cr       = lo0;
        *(float4*)(cr + 4) = lo1;
        float4 hi0 = make_float4(u0.y+bs0.x, u1.y+bs0.y, u2.y+bs0.z, u3.y+bs0.w);
        float4 hi1 = make_float4(u4.y+bs1.x, u5.y+bs1.y, u6.y+bs1.z, u7.y+bs1.w);
        *(float4*)(cr + OO)     = hi0;
        *(float4*)(cr + OO + 4) = hi1;
    }
}

__global__ void __launch_bounds__(256, 2)
gemm1_kernel(const float* __restrict__ W, const float* __restrict__ bias) {
    gemm_body<CF, false>(g_fused, W, bias, g_h, nullptr, nullptr);
}

__global__ void __launch_bounds__(256, 2)
gemm2_kernel(const float* __restrict__ W, const float* __restrict__ bias,
             float* __restrict__ C) {
    gemm_body<OO, true>(g_h, W, bias, C, g_s1, g_t1);
}

// ======================================================================
// Deterministic two-stage column reduction for BN stats (no atomics)
// ======================================================================
__device__ __forceinline__ void col_reduce_body(const float* __restrict__ X) {
    const int c = threadIdx.x;
    const long long base = (long long)blockIdx.x * 256;
    const float* xp = X + base * OO + c;
    float s = 0.f, ss = 0.f;
    #pragma unroll 8
    for (int r = 0; r < 256; r++) {
        float v = xp[(long long)r * OO];
        s += v; ss += v * v;
    }
    g_part[blockIdx.x * 512 + c]       = s;
    g_part[blockIdx.x * 512 + 256 + c] = ss;
}
__global__ void col_reduce_h_kernel() { col_reduce_body(g_h); }
__global__ void col_reduce_x_kernel(const float* __restrict__ X) { col_reduce_body(X); }

__global__ void bn_finalize_kernel(const float* __restrict__ g,
                                   const float* __restrict__ be, int which) {
    const int c = threadIdx.x;
    float s = 0.f, ss = 0.f;
    for (int b = 0; b < 512; b++) {
        s  += g_part[b * 512 + c];
        ss += g_part[b * 512 + 256 + c];
    }
    const float mu  = s * (1.0f / (float)MM);
    const float var = ss * (1.0f / (float)MM) - mu * mu;
    const float inv = rsqrtf(var + 1e-5f);
    const float sc  = g[c] * inv;
    const float sh  = be[c] - mu * sc;
    if (which) { g_s2[c] = sc; g_t2[c] = sh; }
    else       { g_s1[c] = sc; g_t1[c] = sh; }
}

// Final: out = relu(out*scale2 + shift2), in place, vectorized
__global__ void bn_relu_kernel(float* __restrict__ X) {
    const long long i = (long long)blockIdx.x * 256 + threadIdx.x;
    float4 v = ((float4*)X)[i];
    const int c4 = (int)(i & 63);
    const float4 sc = ((const float4*)g_s2)[c4];
    const float4 sh = ((const float4*)g_t2)[c4];
    v.x = fmaxf(fmaf(v.x, sc.x, sh.x), 0.f);
    v.y = fmaxf(fmaf(v.y, sc.y, sh.y), 0.f);
    v.z = fmaxf(fmaf(v.z, sc.z, sh.z), 0.f);
    v.w = fmaxf(fmaf(v.w, sc.w, sh.w), 0.f);
    ((float4*)X)[i] = v;
}

// ======================================================================
extern "C" void kernel_launch(void* const* d_in, const int* in_sizes, int n_in,
                              void* d_out, int out_size) {
    const float* xyz1    = (const float*)d_in[0];
    const float* xyz2    = (const float*)d_in[1];
    const float* points1 = (const float*)d_in[2];
    const float* points2 = (const float*)d_in[3];
    const float* W1      = (const float*)d_in[4];
    const float* b1      = (const float*)d_in[5];
    const float* g1      = (const float*)d_in[6];
    const float* be1     = (const float*)d_in[7];
    const float* W2      = (const float*)d_in[8];
    const float* b2      = (const float*)d_in[9];
    const float* g2      = (const float*)d_in[10];
    const float* be2     = (const float*)d_in[11];
    float* out = (float*)d_out;

    knn_interp_kernel<<<dim3(NN / 256, BB), 256>>>(xyz1, xyz2, points1, points2);
    gemm1_kernel<<<dim3(OO / 128, MM / 128), 256>>>(W1, b1);
    col_reduce_h_kernel<<<512, 256>>>();
    bn_finalize_kernel<<<1, 256>>>(g1, be1, 0);
    gemm2_kernel<<<dim3(OO / 128, MM / 128), 256>>>(W2, b2, out);
    col_reduce_x_kernel<<<512, 256>>>(out);
    bn_finalize_kernel<<<1, 256>>>(g2, be2, 1);
    bn_relu_kernel<<<(MM * OO / 4) / 256, 256>>>(out);
}

// round 5
// speedup vs baseline: 1.6326x; 1.6326x over previous
#include <cuda_runtime.h>
#include <cuda_bf16.h>
#include <cstdint>
#include <math.h>

// Problem constants
#define BB 8
#define NN 16384
#define SSZ 2048
#define C1V 128
#define C2V 256
#define CF 384
#define MM (BB*NN)      /* 131072 rows */
#define OO 256          /* output channels per layer */

// -------- scratch (static device globals; ~331MB total, proven-safe level) --------
// g_ab pool (201MB): phase 1: Ah = g_ab[0..MM*CF), Al = g_ab[MM*CF..2*MM*CF)
//                    phase 2: Bh = g_ab[0..MM*OO), Bl = g_ab[MM*OO..2*MM*OO)
__device__ __align__(16) __nv_bfloat16 g_ab[(size_t)2 * MM * CF];
__device__ __align__(16) float         g_h[(size_t)MM * OO];    // 128MB, layer-1 pre-BN
__device__ __align__(16) __nv_bfloat16 g_w1h[OO * CF], g_w1l[OO * CF];
__device__ __align__(16) __nv_bfloat16 g_w2h[OO * OO], g_w2l[OO * OO];
__device__ __align__(16) float g_part[512 * 512];
__device__ __align__(16) float g_s1[OO], g_t1[OO], g_s2[OO], g_t2[OO];

// ======================================================================
// helpers (NO 'a'-suffix features: mma.sync / ldmatrix / cp.async only)
// ======================================================================
__device__ __forceinline__ uint32_t smem_u32(const void* p) {
    uint32_t a;
    asm("{ .reg .u64 t; cvta.to.shared.u64 t, %1; cvt.u32.u64 %0, t; }" : "=r"(a) : "l"(p));
    return a;
}
__device__ __forceinline__ void cp_async16(uint32_t dst, const void* src) {
    asm volatile("cp.async.cg.shared.global [%0], [%1], 16;" :: "r"(dst), "l"(src));
}
#define CP_COMMIT() asm volatile("cp.async.commit_group;" ::: "memory")
#define CP_WAIT1()  asm volatile("cp.async.wait_group 1;" ::: "memory")
#define CP_WAIT0()  asm volatile("cp.async.wait_group 0;" ::: "memory")

#define LDSM4(r0, r1, r2, r3, addr) \
    asm volatile("ldmatrix.sync.aligned.m8n8.x4.shared.b16 {%0,%1,%2,%3}, [%4];" \
                 : "=r"(r0), "=r"(r1), "=r"(r2), "=r"(r3) : "r"(addr))

__device__ __forceinline__ void mma_bf16(float* c, const uint32_t* a, const uint32_t* b) {
    asm volatile("mma.sync.aligned.m16n8k16.row.col.f32.bf16.bf16.f32 "
                 "{%0,%1,%2,%3}, {%4,%5,%6,%7}, {%8,%9}, {%0,%1,%2,%3};"
                 : "+f"(c[0]), "+f"(c[1]), "+f"(c[2]), "+f"(c[3])
                 : "r"(a[0]), "r"(a[1]), "r"(a[2]), "r"(a[3]), "r"(b[0]), "r"(b[1]));
}

// bf16 hi/lo split
__device__ __forceinline__ void split_bf(float v, __nv_bfloat16& h, __nv_bfloat16& l) {
    h = __float2bfloat16_rn(v);
    l = __float2bfloat16_rn(v - __bfloat162float(h));
}

// ======================================================================
// Kernel 1: 3-NN search + inverse-distance interpolation + concat
// writes bf16 hi/lo split of fused activations into the g_ab pool.
// ======================================================================
__global__ void knn_interp_kernel(const float* __restrict__ xyz1,
                                  const float* __restrict__ xyz2,
                                  const float* __restrict__ points1,
                                  const float* __restrict__ points2) {
    __shared__ float sx[SSZ], sy[SSZ], sz[SSZ];
    __shared__ int   sidx[256][3];
    __shared__ float swt[256][3];

    const int tid = threadIdx.x;
    const int b   = blockIdx.y;
    const int n0  = blockIdx.x * 256;

    const float* x2 = xyz2 + (size_t)b * SSZ * 3;
    for (int i = tid; i < SSZ * 3; i += 256) {
        float v = x2[i];
        int s = i / 3, d = i - s * 3;
        if (d == 0) sx[s] = v; else if (d == 1) sy[s] = v; else sz[s] = v;
    }
    __syncthreads();

    const int n = n0 + tid;
    const float* p = xyz1 + ((size_t)b * NN + n) * 3;
    const float px = p[0], py = p[1], pz = p[2];
    float b0 = 3.4e38f, b1 = 3.4e38f, b2 = 3.4e38f;
    int   j0 = 0, j1 = 0, j2 = 0;
    #pragma unroll 4
    for (int s = 0; s < SSZ; ++s) {
        float dx = px - sx[s], dy = py - sy[s], dz = pz - sz[s];
        float d = dx*dx + dy*dy + dz*dz;
        if (d < b2) {
            if (d < b1) {
                b2 = b1; j2 = j1;
                if (d < b0) { b1 = b0; j1 = j0; b0 = d; j0 = s; }
                else        { b1 = d;  j1 = s; }
            } else { b2 = d; j2 = s; }
        }
    }
    float r0 = 1.f / (sqrtf(b0) + 1e-8f);
    float r1 = 1.f / (sqrtf(b1) + 1e-8f);
    float r2 = 1.f / (sqrtf(b2) + 1e-8f);
    float rs = 1.f / (r0 + r1 + r2);
    sidx[tid][0] = j0; sidx[tid][1] = j1; sidx[tid][2] = j2;
    swt[tid][0] = r0 * rs; swt[tid][1] = r1 * rs; swt[tid][2] = r2 * rs;
    __syncthreads();

    // gather neighbor features, split to bf16 hi/lo, write cols [128,384)
    const float4* p2 = (const float4*)(points2 + (size_t)b * SSZ * C2V);
    __nv_bfloat16* foh = g_ab + ((size_t)b * NN + n0) * CF;
    __nv_bfloat16* fol = foh + (size_t)MM * CF;
    const int lp = tid >> 6;
    const int c4 = tid & 63;
    for (int pb = 0; pb < 256; pb += 4) {
        const int pp = pb + lp;
        const int i0 = sidx[pp][0], i1 = sidx[pp][1], i2 = sidx[pp][2];
        const float w0 = swt[pp][0], w1 = swt[pp][1], w2 = swt[pp][2];
        float4 v0 = p2[(size_t)i0 * 64 + c4];
        float4 v1 = p2[(size_t)i1 * 64 + c4];
        float4 v2 = p2[(size_t)i2 * 64 + c4];
        float4 r;
        r.x = w0*v0.x + w1*v1.x + w2*v2.x;
        r.y = w0*v0.y + w1*v1.y + w2*v2.y;
        r.z = w0*v0.z + w1*v1.z + w2*v2.z;
        r.w = w0*v0.w + w1*v1.w + w2*v2.w;
        union { __nv_bfloat16 bv[4]; uint2 u; } H, L;
        split_bf(r.x, H.bv[0], L.bv[0]);
        split_bf(r.y, H.bv[1], L.bv[1]);
        split_bf(r.z, H.bv[2], L.bv[2]);
        split_bf(r.w, H.bv[3], L.bv[3]);
        const size_t off = (size_t)pp * CF + C1V + c4 * 4;
        *(uint2*)(foh + off) = H.u;
        *(uint2*)(fol + off) = L.u;
    }

    // points1 -> cols [0,128)
    const float4* p1 = (const float4*)(points1 + ((size_t)b * NN + n0) * C1V);
    for (int i = tid; i < 256 * 32; i += 256) {
        const int pp = i >> 5, cc = i & 31;
        float4 v = p1[i];
        union { __nv_bfloat16 bv[4]; uint2 u; } H, L;
        split_bf(v.x, H.bv[0], L.bv[0]);
        split_bf(v.y, H.bv[1], L.bv[1]);
        split_bf(v.z, H.bv[2], L.bv[2]);
        split_bf(v.w, H.bv[3], L.bv[3]);
        const size_t off = (size_t)pp * CF + cc * 4;
        *(uint2*)(foh + off) = H.u;
        *(uint2*)(fol + off) = L.u;
    }
}

// ======================================================================
// Weight convert: fp32 -> bf16 hi/lo (tiny)
// ======================================================================
__global__ void wconvert_kernel(const float* __restrict__ W1,
                                const float* __restrict__ W2) {
    int i = blockIdx.x * 256 + threadIdx.x;
    if (i < OO * CF) { __nv_bfloat16 h, l; split_bf(W1[i], h, l); g_w1h[i] = h; g_w1l[i] = l; }
    if (i < OO * OO) { __nv_bfloat16 h, l; split_bf(W2[i], h, l); g_w2h[i] = h; g_w2l[i] = l; }
}

// ======================================================================
// mma.sync GEMM: C[M,256] = A[M,K] @ W[256,K]^T + bias
// A,W bf16 hi/lo; acc += Ah*Wh + Al*Wh + Ah*Wl  (fp32 accum in regs).
// CTA: 128 rows x 128 cols (grid.y=2 over N), 8 warps (2m x 4n), warp 64x32.
// K-chunks of 32, 3-stage cp.async pipeline.
// smem stage (40960B): Ah[128x80] | Al | Wh[128x80] | Wl  (80B row pitch ->
// 8-row ldmatrix offsets mod 128B are distinct 16B slots: conflict-free).
// Registers: acc 64 + frags 40 + addr ~30 => ~135, no spill.
// ======================================================================
#define ROWP 80
#define TILE_B (128 * ROWP)                  /* 10240 */
#define STAGE_B (4 * TILE_B)                 /* 40960 */
#define GSMEM   (3 * STAGE_B)                /* 122880 */

template<int K>
__device__ __forceinline__ void gemm_body(const __nv_bfloat16* __restrict__ Ah,
                                          const __nv_bfloat16* __restrict__ Al,
                                          const __nv_bfloat16* __restrict__ Wh,
                                          const __nv_bfloat16* __restrict__ Wl,
                                          const float* __restrict__ bias,
                                          float* __restrict__ C) {
    extern __shared__ char smem[];
    constexpr int NC = K / 32;
    const uint32_t sb = smem_u32(smem);
    const int tid  = threadIdx.x;
    const int wid  = tid >> 5, lane = tid & 31;
    const int m0   = blockIdx.x << 7;
    const int n0   = blockIdx.y << 7;
    const int warp_m = (wid & 1) * 64;
    const int warp_n = (wid >> 1) * 32;

    // loader indices: 64 rows per pass, 4x16B chunks per row-chunk
    const int lr = tid >> 2, lkg = tid & 3;
    const uint32_t l_dst = (uint32_t)(lr * ROWP + lkg * 16);
    const size_t   a_src0 = (size_t)(m0 + lr) * K + lkg * 8;
    const size_t   w_src0 = (size_t)(n0 + lr) * K + lkg * 8;

    // frag address components
    const int g = lane >> 3, l7 = lane & 7;
    const uint32_t a_off = (uint32_t)((l7 + (g & 1) * 8) * ROWP + (g >> 1) * 16);
    const uint32_t b_off = (uint32_t)(((g >> 1) * 8 + l7) * ROWP + (g & 1) * 16);

    float acc[4][4][4];
    #pragma unroll
    for (int tm = 0; tm < 4; tm++)
        #pragma unroll
        for (int tn = 0; tn < 4; tn++)
            #pragma unroll
            for (int q = 0; q < 4; q++) acc[tm][tn][q] = 0.f;

    // ---- stage loader: Ah|Al|Wh|Wl, each 128 rows x 32 k (2 passes of 64 rows)
    auto load_stage = [&](int s, int kc) {
        const uint32_t base = sb + s * STAGE_B;
        #pragma unroll
        for (int it = 0; it < 2; it++) {
            const uint32_t d = base + l_dst + it * (64 * ROWP);
            const size_t   ao = a_src0 + (size_t)(it * 64) * K + kc;
            const size_t   wo = w_src0 + (size_t)(it * 64) * K + kc;
            cp_async16(d,              Ah + ao);
            cp_async16(d + TILE_B,     Al + ao);
            cp_async16(d + 2 * TILE_B, Wh + wo);
            cp_async16(d + 3 * TILE_B, Wl + wo);
        }
    };

    load_stage(0, 0);  CP_COMMIT();
    load_stage(1, 32); CP_COMMIT();

    for (int i = 0; i < NC; i++) {
        if (i + 1 < NC) { CP_WAIT1(); } else { CP_WAIT0(); }
        __syncthreads();
        if (i + 2 < NC) { load_stage((i + 2) % 3, (i + 2) * 32); CP_COMMIT(); }

        const uint32_t base = sb + (i % 3) * STAGE_B;
        #pragma unroll
        for (int ks = 0; ks < 2; ks++) {
            uint32_t ah[4][4], al[4][4], w[4][2];
            #pragma unroll
            for (int tm = 0; tm < 4; tm++) {
                const uint32_t ad = base + a_off + (uint32_t)((warp_m + tm * 16) * ROWP + ks * 32);
                LDSM4(ah[tm][0], ah[tm][1], ah[tm][2], ah[tm][3], ad);
                LDSM4(al[tm][0], al[tm][1], al[tm][2], al[tm][3], ad + TILE_B);
            }
            // Wh fragments (32 n-rows = 2 x LDSM4)
            #pragma unroll
            for (int tp = 0; tp < 2; tp++) {
                const uint32_t bd = base + 2 * TILE_B + b_off
                                  + (uint32_t)((warp_n + tp * 16) * ROWP + ks * 32);
                LDSM4(w[2*tp][0], w[2*tp][1], w[2*tp+1][0], w[2*tp+1][1], bd);
            }
            #pragma unroll
            for (int tm = 0; tm < 4; tm++)
                #pragma unroll
                for (int tn = 0; tn < 4; tn++) mma_bf16(acc[tm][tn], ah[tm], w[tn]);
            #pragma unroll
            for (int tm = 0; tm < 4; tm++)
                #pragma unroll
                for (int tn = 0; tn < 4; tn++) mma_bf16(acc[tm][tn], al[tm], w[tn]);
            // Wl fragments into same regs, third product
            #pragma unroll
            for (int tp = 0; tp < 2; tp++) {
                const uint32_t bd = base + 3 * TILE_B + b_off
                                  + (uint32_t)((warp_n + tp * 16) * ROWP + ks * 32);
                LDSM4(w[2*tp][0], w[2*tp][1], w[2*tp+1][0], w[2*tp+1][1], bd);
            }
            #pragma unroll
            for (int tm = 0; tm < 4; tm++)
                #pragma unroll
                for (int tn = 0; tn < 4; tn++) mma_bf16(acc[tm][tn], ah[tm], w[tn]);
        }
    }

    // epilogue: bias + store (fp32)
    float2 bv[4];
    #pragma unroll
    for (int tn = 0; tn < 4; tn++)
        bv[tn] = *(const float2*)(bias + n0 + warp_n + tn * 8 + (lane & 3) * 2);
    #pragma unroll
    for (int tm = 0; tm < 4; tm++) {
        const int r0 = m0 + warp_m + tm * 16 + (lane >> 2);
        float* c0 = C + (size_t)r0 * OO + n0;
        #pragma unroll
        for (int tn = 0; tn < 4; tn++) {
            const int col = warp_n + tn * 8 + (lane & 3) * 2;
            float2 lo = make_float2(acc[tm][tn][0] + bv[tn].x, acc[tm][tn][1] + bv[tn].y);
            float2 hi = make_float2(acc[tm][tn][2] + bv[tn].x, acc[tm][tn][3] + bv[tn].y);
            *(float2*)(c0 + col)          = lo;
            *(float2*)(c0 + 8 * OO + col) = hi;
        }
    }
}

// wrappers: resolve __device__ symbols in device code (host must not take them)
__global__ void __launch_bounds__(256, 1)
gemm1_kernel(const float* __restrict__ bias) {
    gemm_body<CF>(g_ab, g_ab + (size_t)MM * CF, g_w1h, g_w1l, bias, g_h);
}
__global__ void __launch_bounds__(256, 1)
gemm2_kernel(const float* __restrict__ bias, float* __restrict__ C) {
    gemm_body<OO>(g_ab, g_ab + (size_t)MM * OO, g_w2h, g_w2l, bias, C);
}

// ======================================================================
// Deterministic two-stage column reduction for BN stats
// ======================================================================
__device__ __forceinline__ void col_reduce_body(const float* __restrict__ X) {
    const int c = threadIdx.x;
    const size_t base = (size_t)blockIdx.x * 256;
    const float* xp = X + base * OO + c;
    float s = 0.f, ss = 0.f;
    #pragma unroll 8
    for (int r = 0; r < 256; r++) {
        float v = xp[(size_t)r * OO];
        s += v; ss += v * v;
    }
    g_part[blockIdx.x * 512 + c]       = s;
    g_part[blockIdx.x * 512 + 256 + c] = ss;
}
__global__ void col_reduce_h_kernel() { col_reduce_body(g_h); }
__global__ void col_reduce_x_kernel(const float* __restrict__ X) { col_reduce_body(X); }

// finalize: 32 blocks x 8 warps, one warp per channel
__global__ void bn_finalize_kernel(const float* __restrict__ g,
                                   const float* __restrict__ be, int which) {
    const int w = threadIdx.x >> 5, l = threadIdx.x & 31;
    const int c = blockIdx.x * 8 + w;
    float s = 0.f, ss = 0.f;
    #pragma unroll
    for (int b = l; b < 512; b += 32) {
        s  += g_part[b * 512 + c];
        ss += g_part[b * 512 + 256 + c];
    }
    #pragma unroll
    for (int o = 16; o; o >>= 1) {
        s  += __shfl_xor_sync(0xFFFFFFFFu, s, o);
        ss += __shfl_xor_sync(0xFFFFFFFFu, ss, o);
    }
    if (l == 0) {
        const float mu  = s * (1.0f / (float)MM);
        const float var = ss * (1.0f / (float)MM) - mu * mu;
        const float inv = rsqrtf(var + 1e-5f);
        const float sc  = g[c] * inv;
        const float sh  = be[c] - mu * sc;
        if (which) { g_s2[c] = sc; g_t2[c] = sh; }
        else       { g_s1[c] = sc; g_t1[c] = sh; }
    }
}

// bnrelu + bf16 split for layer-2 input; writes into g_ab pool (Ah/Al dead)
__global__ void bnrelu_convert_kernel() {
    const size_t i = (size_t)blockIdx.x * 256 + threadIdx.x;
    float4 v = ((const float4*)g_h)[i];
    const int c4 = (int)(i & 63);
    const float4 sc = ((const float4*)g_s1)[c4];
    const float4 sh = ((const float4*)g_t1)[c4];
    v.x = fmaxf(fmaf(v.x, sc.x, sh.x), 0.f);
    v.y = fmaxf(fmaf(v.y, sc.y, sh.y), 0.f);
    v.z = fmaxf(fmaf(v.z, sc.z, sh.z), 0.f);
    v.w = fmaxf(fmaf(v.w, sc.w, sh.w), 0.f);
    union { __nv_bfloat16 bv[4]; uint2 u; } H, L;
    split_bf(v.x, H.bv[0], L.bv[0]);
    split_bf(v.y, H.bv[1], L.bv[1]);
    split_bf(v.z, H.bv[2], L.bv[2]);
    split_bf(v.w, H.bv[3], L.bv[3]);
    ((uint2*)g_ab)[i]                          = H.u;   // Bh
    ((uint2*)(g_ab + (size_t)MM * OO))[i]      = L.u;   // Bl
}

// Final: out = relu(out*scale2 + shift2) in place
__global__ void bn_relu_kernel(float* __restrict__ X) {
    const size_t i = (size_t)blockIdx.x * 256 + threadIdx.x;
    float4 v = ((float4*)X)[i];
    const int c4 = (int)(i & 63);
    const float4 sc = ((const float4*)g_s2)[c4];
    const float4 sh = ((const float4*)g_t2)[c4];
    v.x = fmaxf(fmaf(v.x, sc.x, sh.x), 0.f);
    v.y = fmaxf(fmaf(v.y, sc.y, sh.y), 0.f);
    v.z = fmaxf(fmaf(v.z, sc.z, sh.z), 0.f);
    v.w = fmaxf(fmaf(v.w, sc.w, sh.w), 0.f);
    ((float4*)X)[i] = v;
}

// ======================================================================
extern "C" void kernel_launch(void* const* d_in, const int* in_sizes, int n_in,
                              void* d_out, int out_size) {
    const float* xyz1    = (const float*)d_in[0];
    const float* xyz2    = (const float*)d_in[1];
    const float* points1 = (const float*)d_in[2];
    const float* points2 = (const float*)d_in[3];
    const float* W1      = (const float*)d_in[4];
    const float* b1      = (const float*)d_in[5];
    const float* g1      = (const float*)d_in[6];
    const float* be1     = (const float*)d_in[7];
    const float* W2      = (const float*)d_in[8];
    const float* b2      = (const float*)d_in[9];
    const float* g2      = (const float*)d_in[10];
    const float* be2     = (const float*)d_in[11];
    float* out = (float*)d_out;

    cudaFuncSetAttribute(gemm1_kernel, cudaFuncAttributeMaxDynamicSharedMemorySize, GSMEM);
    cudaFuncSetAttribute(gemm2_kernel, cudaFuncAttributeMaxDynamicSharedMemorySize, GSMEM);

    wconvert_kernel<<<(OO * CF + 255) / 256, 256>>>(W1, W2);
    knn_interp_kernel<<<dim3(NN / 256, BB), 256>>>(xyz1, xyz2, points1, points2);

    gemm1_kernel<<<dim3(MM / 128, OO / 128), 256, GSMEM>>>(b1);
    col_reduce_h_kernel<<<512, 256>>>();
    bn_finalize_kernel<<<32, 256>>>(g1, be1, 0);
    bnrelu_convert_kernel<<<(MM * OO / 4) / 256, 256>>>();

    gemm2_kernel<<<dim3(MM / 128, OO / 128), 256, GSMEM>>>(b2, out);
    col_reduce_x_kernel<<<512, 256>>>(out);
    bn_finalize_kernel<<<32, 256>>>(g2, be2, 1);
    bn_relu_kernel<<<(MM * OO / 4) / 256, 256>>>(out);
}

// round 7
// speedup vs baseline: 2.0444x; 1.2523x over previous
#include <cuda_runtime.h>
#include <cuda_bf16.h>
#include <cstdint>
#include <math.h>

// Problem constants
#define BB 8
#define NN 16384
#define SSZ 2048
#define C1V 128
#define C2V 256
#define CF 384
#define MM (BB*NN)      /* 131072 rows */
#define OO 256          /* output channels per layer */
#define P2R (BB*SSZ)    /* 16384 points2 rows */

// -------- scratch (static device globals; ~300MB) --------
// g_ab pool (128MB bf16): phase1: p1h = [0, MM*128), p1l = [MM*128, MM*256)
//                         phase2: Bh  = [0, MM*256), Bl  = [MM*256, 2*MM*256)
__device__ __align__(16) __nv_bfloat16 g_ab[(size_t)2 * MM * OO];
__device__ __align__(16) float         g_h[(size_t)MM * OO];       // 128MB pre-BN h
__device__ __align__(16) float         g_p2proj[(size_t)P2R * OO]; // 16.8MB
__device__ __align__(16) __nv_bfloat16 g_p2h[(size_t)P2R * C2V];   // 8.4MB
__device__ __align__(16) __nv_bfloat16 g_p2l[(size_t)P2R * C2V];   // 8.4MB
__device__ __align__(16) float         g_knn[(size_t)MM * 8];      // 4MB idx+w
__device__ __align__(16) __nv_bfloat16 g_w1ah[OO * C1V], g_w1al[OO * C1V];
__device__ __align__(16) __nv_bfloat16 g_w1bh[OO * C2V], g_w1bl[OO * C2V];
__device__ __align__(16) __nv_bfloat16 g_w2h[OO * OO],  g_w2l[OO * OO];
__device__ __align__(16) float g_part[1024 * 512];                 // 2MB
__device__ __align__(16) float g_s1[OO], g_t1[OO], g_s2[OO], g_t2[OO];

// ======================================================================
// helpers (NO 'a'-suffix features)
// ======================================================================
__device__ __forceinline__ uint32_t smem_u32(const void* p) {
    uint32_t a;
    asm("{ .reg .u64 t; cvta.to.shared.u64 t, %1; cvt.u32.u64 %0, t; }" : "=r"(a) : "l"(p));
    return a;
}
__device__ __forceinline__ void cp_async16(uint32_t dst, const void* src) {
    asm volatile("cp.async.cg.shared.global [%0], [%1], 16;" :: "r"(dst), "l"(src));
}
#define CP_COMMIT() asm volatile("cp.async.commit_group;" ::: "memory")
#define CP_WAIT1()  asm volatile("cp.async.wait_group 1;" ::: "memory")
#define CP_WAIT0()  asm volatile("cp.async.wait_group 0;" ::: "memory")

#define LDSM4(r0, r1, r2, r3, addr) \
    asm volatile("ldmatrix.sync.aligned.m8n8.x4.shared.b16 {%0,%1,%2,%3}, [%4];" \
                 : "=r"(r0), "=r"(r1), "=r"(r2), "=r"(r3) : "r"(addr))

__device__ __forceinline__ void mma_bf16(float* c, const uint32_t* a, const uint32_t* b) {
    asm volatile("mma.sync.aligned.m16n8k16.row.col.f32.bf16.bf16.f32 "
                 "{%0,%1,%2,%3}, {%4,%5,%6,%7}, {%8,%9}, {%0,%1,%2,%3};"
                 : "+f"(c[0]), "+f"(c[1]), "+f"(c[2]), "+f"(c[3])
                 : "r"(a[0]), "r"(a[1]), "r"(a[2]), "r"(a[3]), "r"(b[0]), "r"(b[1]));
}

__device__ __forceinline__ void split_bf(float v, __nv_bfloat16& h, __nv_bfloat16& l) {
    h = __float2bfloat16_rn(v);
    l = __float2bfloat16_rn(v - __bfloat162float(h));
}

// ======================================================================
// Kernel 1: 3-NN search -> idx/weights; also converts points1 to bf16 split
// ======================================================================
__global__ void knn_kernel(const float* __restrict__ xyz1,
                           const float* __restrict__ xyz2,
                           const float* __restrict__ points1) {
    __shared__ float sx[SSZ], sy[SSZ], sz[SSZ];

    const int tid = threadIdx.x;
    const int b   = blockIdx.y;
    const int n0  = blockIdx.x * 256;

    const float* x2 = xyz2 + (size_t)b * SSZ * 3;
    for (int i = tid; i < SSZ * 3; i += 256) {
        float v = x2[i];
        int s = i / 3, d = i - s * 3;
        if (d == 0) sx[s] = v; else if (d == 1) sy[s] = v; else sz[s] = v;
    }
    __syncthreads();

    const int n = n0 + tid;
    const float* p = xyz1 + ((size_t)b * NN + n) * 3;
    const float px = p[0], py = p[1], pz = p[2];
    float b0 = 3.4e38f, b1 = 3.4e38f, b2 = 3.4e38f;
    int   j0 = 0, j1 = 0, j2 = 0;
    #pragma unroll 4
    for (int s = 0; s < SSZ; ++s) {
        float dx = px - sx[s], dy = py - sy[s], dz = pz - sz[s];
        float d = dx*dx + dy*dy + dz*dz;
        if (d < b2) {
            if (d < b1) {
                b2 = b1; j2 = j1;
                if (d < b0) { b1 = b0; j1 = j0; b0 = d; j0 = s; }
                else        { b1 = d;  j1 = s; }
            } else { b2 = d; j2 = s; }
        }
    }
    float r0 = 1.f / (sqrtf(b0) + 1e-8f);
    float r1 = 1.f / (sqrtf(b1) + 1e-8f);
    float r2 = 1.f / (sqrtf(b2) + 1e-8f);
    float rs = 1.f / (r0 + r1 + r2);

    const size_t row = (size_t)b * NN + n;
    float4 ia, wa;
    ia.x = __int_as_float(b * SSZ + j0);
    ia.y = __int_as_float(b * SSZ + j1);
    ia.z = __int_as_float(b * SSZ + j2);
    ia.w = 0.f;
    wa.x = r0 * rs; wa.y = r1 * rs; wa.z = r2 * rs; wa.w = 0.f;
    ((float4*)g_knn)[row * 2]     = ia;
    ((float4*)g_knn)[row * 2 + 1] = wa;

    // points1 -> bf16 split (g_ab pool)
    __nv_bfloat16* p1h = g_ab;
    __nv_bfloat16* p1l = g_ab + (size_t)MM * C1V;
    const float4* p1 = (const float4*)(points1 + ((size_t)b * NN + n0) * C1V);
    for (int i = tid; i < 256 * 32; i += 256) {
        const int pp = i >> 5, cc = i & 31;
        float4 v = p1[i];
        union { __nv_bfloat16 bv[4]; uint2 u; } H, L;
        split_bf(v.x, H.bv[0], L.bv[0]);
        split_bf(v.y, H.bv[1], L.bv[1]);
        split_bf(v.z, H.bv[2], L.bv[2]);
        split_bf(v.w, H.bv[3], L.bv[3]);
        const size_t off = ((size_t)b * NN + n0 + pp) * C1V + cc * 4;
        *(uint2*)(p1h + off) = H.u;
        *(uint2*)(p1l + off) = L.u;
    }
}

// ======================================================================
// converts: weights W1 (split into a/b parts) + W2; points2
// ======================================================================
__global__ void wconvert_kernel(const float* __restrict__ W1,
                                const float* __restrict__ W2) {
    int i = blockIdx.x * 256 + threadIdx.x;
    if (i < OO * CF) {
        int o = i / CF, c = i - o * CF;
        __nv_bfloat16 h, l; split_bf(W1[i], h, l);
        if (c < C1V) { g_w1ah[o * C1V + c] = h; g_w1al[o * C1V + c] = l; }
        else         { g_w1bh[o * C2V + c - C1V] = h; g_w1bl[o * C2V + c - C1V] = l; }
    }
    if (i < OO * OO) { __nv_bfloat16 h, l; split_bf(W2[i], h, l); g_w2h[i] = h; g_w2l[i] = l; }
}

__global__ void p2convert_kernel(const float* __restrict__ points2) {
    const size_t i = (size_t)blockIdx.x * 256 + threadIdx.x;   // float4 index
    float4 v = ((const float4*)points2)[i];
    union { __nv_bfloat16 bv[4]; uint2 u; } H, L;
    split_bf(v.x, H.bv[0], L.bv[0]);
    split_bf(v.y, H.bv[1], L.bv[1]);
    split_bf(v.z, H.bv[2], L.bv[2]);
    split_bf(v.w, H.bv[3], L.bv[3]);
    ((uint2*)g_p2h)[i] = H.u;
    ((uint2*)g_p2l)[i] = L.u;
}

// ======================================================================
// mma.sync GEMM: C[M,256] = A[M,K] @ W[256,K]^T (+bias) (+knn gather) (+BN partials)
// CTA 128x128 (grid.y=2 over N), 8 warps (2m x 4n), warp 64x32, 3-stage cp.async.
// ======================================================================
#define ROWP 80
#define TILE_B (128 * ROWP)
#define STAGE_B (4 * TILE_B)
#define GSMEM   (3 * STAGE_B)

template<int K, bool BIAS, bool GATHER, bool PART>
__device__ __forceinline__ void gemm_body(const __nv_bfloat16* __restrict__ Ah,
                                          const __nv_bfloat16* __restrict__ Al,
                                          const __nv_bfloat16* __restrict__ Wh,
                                          const __nv_bfloat16* __restrict__ Wl,
                                          const float* __restrict__ bias,
                                          float* __restrict__ C) {
    extern __shared__ char smem[];
    constexpr int NC = K / 32;
    const uint32_t sb = smem_u32(smem);
    const int tid  = threadIdx.x;
    const int wid  = tid >> 5, lane = tid & 31;
    const int m0   = blockIdx.x << 7;
    const int n0   = blockIdx.y << 7;
    const int warp_m = (wid & 1) * 64;
    const int warp_n = (wid >> 1) * 32;

    const int lr = tid >> 2, lkg = tid & 3;
    const uint32_t l_dst = (uint32_t)(lr * ROWP + lkg * 16);
    const size_t   a_src0 = (size_t)(m0 + lr) * K + lkg * 8;
    const size_t   w_src0 = (size_t)(n0 + lr) * K + lkg * 8;

    const int g = lane >> 3, l7 = lane & 7;
    const uint32_t a_off = (uint32_t)((l7 + (g & 1) * 8) * ROWP + (g >> 1) * 16);
    const uint32_t b_off = (uint32_t)(((g >> 1) * 8 + l7) * ROWP + (g & 1) * 16);

    float acc[4][4][4];
    #pragma unroll
    for (int tm = 0; tm < 4; tm++)
        #pragma unroll
        for (int tn = 0; tn < 4; tn++)
            #pragma unroll
            for (int q = 0; q < 4; q++) acc[tm][tn][q] = 0.f;

    auto load_stage = [&](int s, int kc) {
        const uint32_t base = sb + s * STAGE_B;
        #pragma unroll
        for (int it = 0; it < 2; it++) {
            const uint32_t d = base + l_dst + it * (64 * ROWP);
            const size_t   ao = a_src0 + (size_t)(it * 64) * K + kc;
            const size_t   wo = w_src0 + (size_t)(it * 64) * K + kc;
            cp_async16(d,              Ah + ao);
            cp_async16(d + TILE_B,     Al + ao);
            cp_async16(d + 2 * TILE_B, Wh + wo);
            cp_async16(d + 3 * TILE_B, Wl + wo);
        }
    };

    load_stage(0, 0);  CP_COMMIT();
    load_stage(1, 32); CP_COMMIT();

    for (int i = 0; i < NC; i++) {
        if (i + 1 < NC) { CP_WAIT1(); } else { CP_WAIT0(); }
        __syncthreads();
        if (i + 2 < NC) { load_stage((i + 2) % 3, (i + 2) * 32); CP_COMMIT(); }

        const uint32_t base = sb + (i % 3) * STAGE_B;
        #pragma unroll
        for (int ks = 0; ks < 2; ks++) {
            uint32_t ah[4][4], al[4][4], w[4][2];
            #pragma unroll
            for (int tm = 0; tm < 4; tm++) {
                const uint32_t ad = base + a_off + (uint32_t)((warp_m + tm * 16) * ROWP + ks * 32);
                LDSM4(ah[tm][0], ah[tm][1], ah[tm][2], ah[tm][3], ad);
                LDSM4(al[tm][0], al[tm][1], al[tm][2], al[tm][3], ad + TILE_B);
            }
            #pragma unroll
            for (int tp = 0; tp < 2; tp++) {
                const uint32_t bd = base + 2 * TILE_B + b_off
                                  + (uint32_t)((warp_n + tp * 16) * ROWP + ks * 32);
                LDSM4(w[2*tp][0], w[2*tp][1], w[2*tp+1][0], w[2*tp+1][1], bd);
            }
            #pragma unroll
            for (int tm = 0; tm < 4; tm++)
                #pragma unroll
                for (int tn = 0; tn < 4; tn++) mma_bf16(acc[tm][tn], ah[tm], w[tn]);
            #pragma unroll
            for (int tm = 0; tm < 4; tm++)
                #pragma unroll
                for (int tn = 0; tn < 4; tn++) mma_bf16(acc[tm][tn], al[tm], w[tn]);
            #pragma unroll
            for (int tp = 0; tp < 2; tp++) {
                const uint32_t bd = base + 3 * TILE_B + b_off
                                  + (uint32_t)((warp_n + tp * 16) * ROWP + ks * 32);
                LDSM4(w[2*tp][0], w[2*tp][1], w[2*tp+1][0], w[2*tp+1][1], bd);
            }
            #pragma unroll
            for (int tm = 0; tm < 4; tm++)
                #pragma unroll
                for (int tn = 0; tn < 4; tn++) mma_bf16(acc[tm][tn], ah[tm], w[tn]);
        }
    }

    // ---- epilogue ----
    if (BIAS) {
        #pragma unroll
        for (int tn = 0; tn < 4; tn++) {
            float2 bv = *(const float2*)(bias + n0 + warp_n + tn * 8 + (lane & 3) * 2);
            #pragma unroll
            for (int tm = 0; tm < 4; tm++) {
                acc[tm][tn][0] += bv.x; acc[tm][tn][1] += bv.y;
                acc[tm][tn][2] += bv.x; acc[tm][tn][3] += bv.y;
            }
        }
    }

    if (GATHER) {
        #pragma unroll
        for (int tm = 0; tm < 4; tm++) {
            const int r_lo = m0 + warp_m + tm * 16 + (lane >> 2);
            const int r_hi = r_lo + 8;
            float4 ia = ((const float4*)g_knn)[(size_t)r_lo * 2];
            float4 wa = ((const float4*)g_knn)[(size_t)r_lo * 2 + 1];
            float4 ib = ((const float4*)g_knn)[(size_t)r_hi * 2];
            float4 wb = ((const float4*)g_knn)[(size_t)r_hi * 2 + 1];
            const int   gl[3] = { __float_as_int(ia.x), __float_as_int(ia.y), __float_as_int(ia.z) };
            const float wl[3] = { wa.x, wa.y, wa.z };
            const int   gh[3] = { __float_as_int(ib.x), __float_as_int(ib.y), __float_as_int(ib.z) };
            const float wh[3] = { wb.x, wb.y, wb.z };
            #pragma unroll
            for (int k = 0; k < 3; k++) {
                const float* pl = g_p2proj + (size_t)gl[k] * OO + n0;
                const float* ph = g_p2proj + (size_t)gh[k] * OO + n0;
                #pragma unroll
                for (int tn = 0; tn < 4; tn++) {
                    const int col = warp_n + tn * 8 + (lane & 3) * 2;
                    float2 vl = *(const float2*)(pl + col);
                    float2 vh = *(const float2*)(ph + col);
                    acc[tm][tn][0] += wl[k] * vl.x; acc[tm][tn][1] += wl[k] * vl.y;
                    acc[tm][tn][2] += wh[k] * vh.x; acc[tm][tn][3] += wh[k] * vh.y;
                }
            }
        }
    }

    if (PART) {   // deterministic per-CTA BN partials (includes bias & gather)
        __syncthreads();      // stage smem dead; safe to reuse
        float* sP  = (float*)smem;      // [2][128]
        float* ssP = sP + 256;          // [2][128]
        #pragma unroll
        for (int tn = 0; tn < 4; tn++) {
            #pragma unroll
            for (int p = 0; p < 2; p++) {
                float s = 0.f, ss = 0.f;
                #pragma unroll
                for (int tm = 0; tm < 4; tm++) {
                    float a = acc[tm][tn][p], b = acc[tm][tn][2 + p];
                    s += a + b; ss += a * a + b * b;
                }
                #pragma unroll
                for (int o = 4; o <= 16; o <<= 1) {
                    s  += __shfl_xor_sync(0xFFFFFFFFu, s, o);
                    ss += __shfl_xor_sync(0xFFFFFFFFu, ss, o);
                }
                if (lane < 4) {
                    const int cl = warp_n + tn * 8 + (lane & 3) * 2 + p;
                    sP [(wid & 1) * 128 + cl] = s;
                    ssP[(wid & 1) * 128 + cl] = ss;
                }
            }
        }
        __syncthreads();
        if (tid < 128) {
            const float s  = sP[tid]  + sP[128 + tid];
            const float ss = ssP[tid] + ssP[128 + tid];
            g_part[(size_t)blockIdx.x * 512 + n0 + tid]       = s;
            g_part[(size_t)blockIdx.x * 512 + 256 + n0 + tid] = ss;
        }
    }

    // store C (fp32)
    #pragma unroll
    for (int tm = 0; tm < 4; tm++) {
        const int r0 = m0 + warp_m + tm * 16 + (lane >> 2);
        float* c0 = C + (size_t)r0 * OO + n0;
        #pragma unroll
        for (int tn = 0; tn < 4; tn++) {
            const int col = warp_n + tn * 8 + (lane & 3) * 2;
            *(float2*)(c0 + col)          = make_float2(acc[tm][tn][0], acc[tm][tn][1]);
            *(float2*)(c0 + 8 * OO + col) = make_float2(acc[tm][tn][2], acc[tm][tn][3]);
        }
    }
}

__global__ void __launch_bounds__(256, 1)
p2proj_kernel() {
    gemm_body<C2V, false, false, false>(g_p2h, g_p2l, g_w1bh, g_w1bl, nullptr, g_p2proj);
}
__global__ void __launch_bounds__(256, 1)
gemm1_kernel(const float* __restrict__ bias) {
    gemm_body<C1V, true, true, true>(g_ab, g_ab + (size_t)MM * C1V, g_w1ah, g_w1al, bias, g_h);
}
__global__ void __launch_bounds__(256, 1)
gemm2_kernel(const float* __restrict__ bias, float* __restrict__ C) {
    gemm_body<OO, true, false, true>(g_ab, g_ab + (size_t)MM * OO, g_w2h, g_w2l, bias, C);
}

// ======================================================================
// BN finalize over 1024 m-block partials; 32 blocks x 8 warps
// ======================================================================
__global__ void bn_finalize_kernel(const float* __restrict__ g,
                                   const float* __restrict__ be, int which) {
    const int w = threadIdx.x >> 5, l = threadIdx.x & 31;
    const int c = blockIdx.x * 8 + w;
    float s = 0.f, ss = 0.f;
    for (int b = l; b < 1024; b += 32) {
        s  += g_part[(size_t)b * 512 + c];
        ss += g_part[(size_t)b * 512 + 256 + c];
    }
    #pragma unroll
    for (int o = 16; o; o >>= 1) {
        s  += __shfl_xor_sync(0xFFFFFFFFu, s, o);
        ss += __shfl_xor_sync(0xFFFFFFFFu, ss, o);
    }
    if (l == 0) {
        const float mu  = s * (1.0f / (float)MM);
        const float var = ss * (1.0f / (float)MM) - mu * mu;
        const float inv = rsqrtf(var + 1e-5f);
        const float sc  = g[c] * inv;
        const float sh  = be[c] - mu * sc;
        if (which) { g_s2[c] = sc; g_t2[c] = sh; }
        else       { g_s1[c] = sc; g_t1[c] = sh; }
    }
}

// bnrelu + bf16 split for layer-2 input (into g_ab pool; p1 split is dead)
__global__ void bnrelu_convert_kernel() {
    const size_t i = (size_t)blockIdx.x * 256 + threadIdx.x;
    float4 v = ((const float4*)g_h)[i];
    const int c4 = (int)(i & 63);
    const float4 sc = ((const float4*)g_s1)[c4];
    const float4 sh = ((const float4*)g_t1)[c4];
    v.x = fmaxf(fmaf(v.x, sc.x, sh.x), 0.f);
    v.y = fmaxf(fmaf(v.y, sc.y, sh.y), 0.f);
    v.z = fmaxf(fmaf(v.z, sc.z, sh.z), 0.f);
    v.w = fmaxf(fmaf(v.w, sc.w, sh.w), 0.f);
    union { __nv_bfloat16 bv[4]; uint2 u; } H, L;
    split_bf(v.x, H.bv[0], L.bv[0]);
    split_bf(v.y, H.bv[1], L.bv[1]);
    split_bf(v.z, H.bv[2], L.bv[2]);
    split_bf(v.w, H.bv[3], L.bv[3]);
    ((uint2*)g_ab)[i]                     = H.u;   // Bh
    ((uint2*)(g_ab + (size_t)MM * OO))[i] = L.u;   // Bl
}

// Final: out = relu(out*scale2 + shift2) in place
__global__ void bn_relu_kernel(float* __restrict__ X) {
    const size_t i = (size_t)blockIdx.x * 256 + threadIdx.x;
    float4 v = ((float4*)X)[i];
    const int c4 = (int)(i & 63);
    const float4 sc = ((const float4*)g_s2)[c4];
    const float4 sh = ((const float4*)g_t2)[c4];
    v.x = fmaxf(fmaf(v.x, sc.x, sh.x), 0.f);
    v.y = fmaxf(fmaf(v.y, sc.y, sh.y), 0.f);
    v.z = fmaxf(fmaf(v.z, sc.z, sh.z), 0.f);
    v.w = fmaxf(fmaf(v.w, sc.w, sh.w), 0.f);
    ((float4*)X)[i] = v;
}

// ======================================================================
extern "C" void kernel_launch(void* const* d_in, const int* in_sizes, int n_in,
                              void* d_out, int out_size) {
    const float* xyz1    = (const float*)d_in[0];
    const float* xyz2    = (const float*)d_in[1];
    const float* points1 = (const float*)d_in[2];
    const float* points2 = (const float*)d_in[3];
    const float* W1      = (const float*)d_in[4];
    const float* b1      = (const float*)d_in[5];
    const float* g1      = (const float*)d_in[6];
    const float* be1     = (const float*)d_in[7];
    const float* W2      = (const float*)d_in[8];
    const float* b2      = (const float*)d_in[9];
    const float* g2      = (const float*)d_in[10];
    const float* be2     = (const float*)d_in[11];
    float* out = (float*)d_out;

    cudaFuncSetAttribute(p2proj_kernel, cudaFuncAttributeMaxDynamicSharedMemorySize, GSMEM);
    cudaFuncSetAttribute(gemm1_kernel,  cudaFuncAttributeMaxDynamicSharedMemorySize, GSMEM);
    cudaFuncSetAttribute(gemm2_kernel,  cudaFuncAttributeMaxDynamicSharedMemorySize, GSMEM);

    wconvert_kernel<<<(OO * CF + 255) / 256, 256>>>(W1, W2);
    p2convert_kernel<<<(P2R * C2V / 4) / 256, 256>>>(points2);
    knn_kernel<<<dim3(NN / 256, BB), 256>>>(xyz1, xyz2, points1);

    p2proj_kernel<<<dim3(P2R / 128, OO / 128), 256, GSMEM>>>();
    gemm1_kernel<<<dim3(MM / 128, OO / 128), 256, GSMEM>>>(b1);
    bn_finalize_kernel<<<32, 256>>>(g1, be1, 0);
    bnrelu_convert_kernel<<<(MM * OO / 4) / 256, 256>>>();

    gemm2_kernel<<<dim3(MM / 128, OO / 128), 256, GSMEM>>>(b2, out);
    bn_finalize_kernel<<<32, 256>>>(g2, be2, 1);
    bn_relu_kernel<<<(MM * OO / 4) / 256, 256>>>(out);
}

// round 8
// speedup vs baseline: 2.0809x; 1.0178x over previous
#include <cuda_runtime.h>
#include <cuda_bf16.h>
#include <cstdint>
#include <math.h>

// Problem constants
#define BB 8
#define NN 16384
#define SSZ 2048
#define C1V 128
#define C2V 256
#define CF 384
#define MM (BB*NN)      /* 131072 rows */
#define OO 256          /* output channels per layer */
#define P2R (BB*SSZ)    /* 16384 points2 rows */

// -------- scratch (static device globals; ~237MB) --------
__device__ __align__(16) __nv_bfloat16 g_p1h[(size_t)MM * C1V];    // 33.5MB
__device__ __align__(16) __nv_bfloat16 g_p1l[(size_t)MM * C1V];    // 33.5MB
__device__ __align__(16) float         g_h[(size_t)MM * OO];       // 134MB pre-BN h
__device__ __align__(16) float         g_p2proj[(size_t)P2R * OO]; // 16.8MB
__device__ __align__(16) __nv_bfloat16 g_p2h[(size_t)P2R * C2V];   // 8.4MB
__device__ __align__(16) __nv_bfloat16 g_p2l[(size_t)P2R * C2V];   // 8.4MB
__device__ __align__(16) float         g_knn[(size_t)MM * 8];      // 4MB idx+w
__device__ __align__(16) __nv_bfloat16 g_w1ah[OO * C1V], g_w1al[OO * C1V];
__device__ __align__(16) __nv_bfloat16 g_w1bh[OO * C2V], g_w1bl[OO * C2V];
__device__ __align__(16) __nv_bfloat16 g_w2h[OO * OO],  g_w2l[OO * OO];
__device__ __align__(16) float g_part[1024 * 512];                 // 2MB
__device__ __align__(16) float g_s1[OO], g_t1[OO], g_s2[OO], g_t2[OO];

// ======================================================================
// helpers (NO 'a'-suffix features)
// ======================================================================
__device__ __forceinline__ uint32_t smem_u32(const void* p) {
    uint32_t a;
    asm("{ .reg .u64 t; cvta.to.shared.u64 t, %1; cvt.u32.u64 %0, t; }" : "=r"(a) : "l"(p));
    return a;
}
__device__ __forceinline__ void cp_async16(uint32_t dst, const void* src) {
    asm volatile("cp.async.cg.shared.global [%0], [%1], 16;" :: "r"(dst), "l"(src));
}
#define CP_COMMIT() asm volatile("cp.async.commit_group;" ::: "memory")
#define CP_WAIT1()  asm volatile("cp.async.wait_group 1;" ::: "memory")
#define CP_WAIT0()  asm volatile("cp.async.wait_group 0;" ::: "memory")

#define LDSM4(r0, r1, r2, r3, addr) \
    asm volatile("ldmatrix.sync.aligned.m8n8.x4.shared.b16 {%0,%1,%2,%3}, [%4];" \
                 : "=r"(r0), "=r"(r1), "=r"(r2), "=r"(r3) : "r"(addr))

#define STS64(addr, v0, v1) \
    asm volatile("st.shared.v2.b32 [%0], {%1,%2};" :: "r"(addr), "r"(v0), "r"(v1))

__device__ __forceinline__ void mma_bf16(float* c, const uint32_t* a, const uint32_t* b) {
    asm volatile("mma.sync.aligned.m16n8k16.row.col.f32.bf16.bf16.f32 "
                 "{%0,%1,%2,%3}, {%4,%5,%6,%7}, {%8,%9}, {%0,%1,%2,%3};"
                 : "+f"(c[0]), "+f"(c[1]), "+f"(c[2]), "+f"(c[3])
                 : "r"(a[0]), "r"(a[1]), "r"(a[2]), "r"(a[3]), "r"(b[0]), "r"(b[1]));
}

__device__ __forceinline__ void split_bf(float v, __nv_bfloat16& h, __nv_bfloat16& l) {
    h = __float2bfloat16_rn(v);
    l = __float2bfloat16_rn(v - __bfloat162float(h));
}

// ======================================================================
// Kernel 1: 3-NN search -> idx/weights; also converts points1 to bf16 split
// ======================================================================
__global__ void knn_kernel(const float* __restrict__ xyz1,
                           const float* __restrict__ xyz2,
                           const float* __restrict__ points1) {
    __shared__ float4 s4[SSZ];   // 32KB SoA (x,y,z,_) for 1 LDS.128 per candidate

    const int tid = threadIdx.x;
    const int b   = blockIdx.y;
    const int n0  = blockIdx.x * 256;

    const float* x2 = xyz2 + (size_t)b * SSZ * 3;
    for (int s = tid; s < SSZ; s += 256) {
        s4[s] = make_float4(x2[3*s], x2[3*s+1], x2[3*s+2], 0.f);
    }
    __syncthreads();

    const int n = n0 + tid;
    const float* p = xyz1 + ((size_t)b * NN + n) * 3;
    const float px = p[0], py = p[1], pz = p[2];
    float b0 = 3.4e38f, b1 = 3.4e38f, b2 = 3.4e38f;
    int   j0 = 0, j1 = 0, j2 = 0;
    #pragma unroll 4
    for (int s = 0; s < SSZ; ++s) {
        float4 q = s4[s];
        float dx = px - q.x, dy = py - q.y, dz = pz - q.z;
        float d = dx*dx + dy*dy + dz*dz;
        if (d < b2) {
            if (d < b1) {
                b2 = b1; j2 = j1;
                if (d < b0) { b1 = b0; j1 = j0; b0 = d; j0 = s; }
                else        { b1 = d;  j1 = s; }
            } else { b2 = d; j2 = s; }
        }
    }
    float r0 = 1.f / (sqrtf(b0) + 1e-8f);
    float r1 = 1.f / (sqrtf(b1) + 1e-8f);
    float r2 = 1.f / (sqrtf(b2) + 1e-8f);
    float rs = 1.f / (r0 + r1 + r2);

    const size_t row = (size_t)b * NN + n;
    float4 ia, wa;
    ia.x = __int_as_float(b * SSZ + j0);
    ia.y = __int_as_float(b * SSZ + j1);
    ia.z = __int_as_float(b * SSZ + j2);
    ia.w = 0.f;
    wa.x = r0 * rs; wa.y = r1 * rs; wa.z = r2 * rs; wa.w = 0.f;
    ((float4*)g_knn)[row * 2]     = ia;
    ((float4*)g_knn)[row * 2 + 1] = wa;

    // points1 -> bf16 split
    const float4* p1 = (const float4*)(points1 + ((size_t)b * NN + n0) * C1V);
    for (int i = tid; i < 256 * 32; i += 256) {
        float4 v = p1[i];
        union { __nv_bfloat16 bv[4]; uint2 u; } H, L;
        split_bf(v.x, H.bv[0], L.bv[0]);
        split_bf(v.y, H.bv[1], L.bv[1]);
        split_bf(v.z, H.bv[2], L.bv[2]);
        split_bf(v.w, H.bv[3], L.bv[3]);
        const size_t off4 = ((size_t)b * NN + n0) * 32 + i;   // uint2 index
        ((uint2*)g_p1h)[off4] = H.u;
        ((uint2*)g_p1l)[off4] = L.u;
    }
}

// ======================================================================
// converts: weights W1 (split into a/b parts) + W2; points2
// ======================================================================
__global__ void wconvert_kernel(const float* __restrict__ W1,
                                const float* __restrict__ W2) {
    int i = blockIdx.x * 256 + threadIdx.x;
    if (i < OO * CF) {
        int o = i / CF, c = i - o * CF;
        __nv_bfloat16 h, l; split_bf(W1[i], h, l);
        if (c < C1V) { g_w1ah[o * C1V + c] = h; g_w1al[o * C1V + c] = l; }
        else         { g_w1bh[o * C2V + c - C1V] = h; g_w1bl[o * C2V + c - C1V] = l; }
    }
    if (i < OO * OO) { __nv_bfloat16 h, l; split_bf(W2[i], h, l); g_w2h[i] = h; g_w2l[i] = l; }
}

__global__ void p2convert_kernel(const float* __restrict__ points2) {
    const size_t i = (size_t)blockIdx.x * 256 + threadIdx.x;   // float4 index
    float4 v = ((const float4*)points2)[i];
    union { __nv_bfloat16 bv[4]; uint2 u; } H, L;
    split_bf(v.x, H.bv[0], L.bv[0]);
    split_bf(v.y, H.bv[1], L.bv[1]);
    split_bf(v.z, H.bv[2], L.bv[2]);
    split_bf(v.w, H.bv[3], L.bv[3]);
    ((uint2*)g_p2h)[i] = H.u;
    ((uint2*)g_p2l)[i] = L.u;
}

// ======================================================================
// Shared GEMM compute-core pieces (CTA 128x128, 8 warps 2m x 4n, warp 64x32)
// smem stage: Ah[128xROWP] | Al | Wh | Wl
// ======================================================================
#define ROWP 80
#define TILE_B (128 * ROWP)
#define STAGE_B (4 * TILE_B)
#define GSMEM   (3 * STAGE_B)
#define GSMEM2  (2 * STAGE_B)

struct FragIdx {
    uint32_t a_off, b_off;
};
__device__ __forceinline__ FragIdx frag_idx(int lane) {
    const int g = lane >> 3, l7 = lane & 7;
    FragIdx f;
    f.a_off = (uint32_t)((l7 + (g & 1) * 8) * ROWP + (g >> 1) * 16);
    f.b_off = (uint32_t)(((g >> 1) * 8 + l7) * ROWP + (g & 1) * 16);
    return f;
}

// one stage of MMA compute (2 ks-steps) from stage base
__device__ __forceinline__ void compute_stage(uint32_t base, int warp_m, int warp_n,
                                              const FragIdx& f, float acc[4][4][4]) {
    #pragma unroll
    for (int ks = 0; ks < 2; ks++) {
        uint32_t ah[4][4], al[4][4], w[4][2];
        #pragma unroll
        for (int tm = 0; tm < 4; tm++) {
            const uint32_t ad = base + f.a_off + (uint32_t)((warp_m + tm * 16) * ROWP + ks * 32);
            LDSM4(ah[tm][0], ah[tm][1], ah[tm][2], ah[tm][3], ad);
            LDSM4(al[tm][0], al[tm][1], al[tm][2], al[tm][3], ad + TILE_B);
        }
        #pragma unroll
        for (int tp = 0; tp < 2; tp++) {
            const uint32_t bd = base + 2 * TILE_B + f.b_off
                              + (uint32_t)((warp_n + tp * 16) * ROWP + ks * 32);
            LDSM4(w[2*tp][0], w[2*tp][1], w[2*tp+1][0], w[2*tp+1][1], bd);
        }
        #pragma unroll
        for (int tm = 0; tm < 4; tm++)
            #pragma unroll
            for (int tn = 0; tn < 4; tn++) mma_bf16(acc[tm][tn], ah[tm], w[tn]);
        #pragma unroll
        for (int tm = 0; tm < 4; tm++)
            #pragma unroll
            for (int tn = 0; tn < 4; tn++) mma_bf16(acc[tm][tn], al[tm], w[tn]);
        #pragma unroll
        for (int tp = 0; tp < 2; tp++) {
            const uint32_t bd = base + 3 * TILE_B + f.b_off
                              + (uint32_t)((warp_n + tp * 16) * ROWP + ks * 32);
            LDSM4(w[2*tp][0], w[2*tp][1], w[2*tp+1][0], w[2*tp+1][1], bd);
        }
        #pragma unroll
        for (int tm = 0; tm < 4; tm++)
            #pragma unroll
            for (int tn = 0; tn < 4; tn++) mma_bf16(acc[tm][tn], ah[tm], w[tn]);
    }
}

// epilogue: optional bias, gather, BN-partials, then store
template<bool BIAS, bool GATHER, bool PART>
__device__ __forceinline__ void gemm_epilogue(float acc[4][4][4], char* smem,
                                              int tid, int wid, int lane,
                                              int m0, int n0, int warp_m, int warp_n,
                                              const float* bias, float* C) {
    if (BIAS) {
        #pragma unroll
        for (int tn = 0; tn < 4; tn++) {
            float2 bv = *(const float2*)(bias + n0 + warp_n + tn * 8 + (lane & 3) * 2);
            #pragma unroll
            for (int tm = 0; tm < 4; tm++) {
                acc[tm][tn][0] += bv.x; acc[tm][tn][1] += bv.y;
                acc[tm][tn][2] += bv.x; acc[tm][tn][3] += bv.y;
            }
        }
    }
    if (GATHER) {
        #pragma unroll
        for (int tm = 0; tm < 4; tm++) {
            const int r_lo = m0 + warp_m + tm * 16 + (lane >> 2);
            const int r_hi = r_lo + 8;
            float4 ia = ((const float4*)g_knn)[(size_t)r_lo * 2];
            float4 wa = ((const float4*)g_knn)[(size_t)r_lo * 2 + 1];
            float4 ib = ((const float4*)g_knn)[(size_t)r_hi * 2];
            float4 wb = ((const float4*)g_knn)[(size_t)r_hi * 2 + 1];
            const int   gl[3] = { __float_as_int(ia.x), __float_as_int(ia.y), __float_as_int(ia.z) };
            const float wl[3] = { wa.x, wa.y, wa.z };
            const int   gh[3] = { __float_as_int(ib.x), __float_as_int(ib.y), __float_as_int(ib.z) };
            const float wh[3] = { wb.x, wb.y, wb.z };
            #pragma unroll
            for (int k = 0; k < 3; k++) {
                const float* pl = g_p2proj + (size_t)gl[k] * OO + n0;
                const float* ph = g_p2proj + (size_t)gh[k] * OO + n0;
                #pragma unroll
                for (int tn = 0; tn < 4; tn++) {
                    const int col = warp_n + tn * 8 + (lane & 3) * 2;
                    float2 vl = *(const float2*)(pl + col);
                    float2 vh = *(const float2*)(ph + col);
                    acc[tm][tn][0] += wl[k] * vl.x; acc[tm][tn][1] += wl[k] * vl.y;
                    acc[tm][tn][2] += wh[k] * vh.x; acc[tm][tn][3] += wh[k] * vh.y;
                }
            }
        }
    }
    if (PART) {
        __syncthreads();
        float* sP  = (float*)smem;
        float* ssP = sP + 256;
        #pragma unroll
        for (int tn = 0; tn < 4; tn++) {
            #pragma unroll
            for (int p = 0; p < 2; p++) {
                float s = 0.f, ss = 0.f;
                #pragma unroll
                for (int tm = 0; tm < 4; tm++) {
                    float a = acc[tm][tn][p], b = acc[tm][tn][2 + p];
                    s += a + b; ss += a * a + b * b;
                }
                #pragma unroll
                for (int o = 4; o <= 16; o <<= 1) {
                    s  += __shfl_xor_sync(0xFFFFFFFFu, s, o);
                    ss += __shfl_xor_sync(0xFFFFFFFFu, ss, o);
                }
                if (lane < 4) {
                    const int cl = warp_n + tn * 8 + (lane & 3) * 2 + p;
                    sP [(wid & 1) * 128 + cl] = s;
                    ssP[(wid & 1) * 128 + cl] = ss;
                }
            }
        }
        __syncthreads();
        if (tid < 128) {
            g_part[(size_t)blockIdx.x * 512 + n0 + tid]       = sP[tid]  + sP[128 + tid];
            g_part[(size_t)blockIdx.x * 512 + 256 + n0 + tid] = ssP[tid] + ssP[128 + tid];
        }
    }
    #pragma unroll
    for (int tm = 0; tm < 4; tm++) {
        const int r0 = m0 + warp_m + tm * 16 + (lane >> 2);
        float* c0 = C + (size_t)r0 * OO + n0;
        #pragma unroll
        for (int tn = 0; tn < 4; tn++) {
            const int col = warp_n + tn * 8 + (lane & 3) * 2;
            *(float2*)(c0 + col)          = make_float2(acc[tm][tn][0], acc[tm][tn][1]);
            *(float2*)(c0 + 8 * OO + col) = make_float2(acc[tm][tn][2], acc[tm][tn][3]);
        }
    }
}

// ----- generic bf16-split GEMM (cp.async A and W), 3-stage -----
template<int K, bool BIAS, bool GATHER, bool PART>
__device__ __forceinline__ void gemm_body(const __nv_bfloat16* __restrict__ Ah,
                                          const __nv_bfloat16* __restrict__ Al,
                                          const __nv_bfloat16* __restrict__ Wh,
                                          const __nv_bfloat16* __restrict__ Wl,
                                          const float* __restrict__ bias,
                                          float* __restrict__ C) {
    extern __shared__ char smem[];
    constexpr int NC = K / 32;
    const uint32_t sb = smem_u32(smem);
    const int tid  = threadIdx.x;
    const int wid  = tid >> 5, lane = tid & 31;
    const int m0   = blockIdx.x << 7;
    const int n0   = blockIdx.y << 7;
    const int warp_m = (wid & 1) * 64;
    const int warp_n = (wid >> 1) * 32;

    const int lr = tid >> 2, lkg = tid & 3;
    const uint32_t l_dst = (uint32_t)(lr * ROWP + lkg * 16);
    const size_t   a_src0 = (size_t)(m0 + lr) * K + lkg * 8;
    const size_t   w_src0 = (size_t)(n0 + lr) * K + lkg * 8;
    const FragIdx f = frag_idx(lane);

    float acc[4][4][4];
    #pragma unroll
    for (int tm = 0; tm < 4; tm++)
        #pragma unroll
        for (int tn = 0; tn < 4; tn++)
            #pragma unroll
            for (int q = 0; q < 4; q++) acc[tm][tn][q] = 0.f;

    auto load_stage = [&](int s, int kc) {
        const uint32_t base = sb + s * STAGE_B;
        #pragma unroll
        for (int it = 0; it < 2; it++) {
            const uint32_t d = base + l_dst + it * (64 * ROWP);
            const size_t   ao = a_src0 + (size_t)(it * 64) * K + kc;
            const size_t   wo = w_src0 + (size_t)(it * 64) * K + kc;
            cp_async16(d,              Ah + ao);
            cp_async16(d + TILE_B,     Al + ao);
            cp_async16(d + 2 * TILE_B, Wh + wo);
            cp_async16(d + 3 * TILE_B, Wl + wo);
        }
    };

    load_stage(0, 0);  CP_COMMIT();
    load_stage(1, 32); CP_COMMIT();

    for (int i = 0; i < NC; i++) {
        if (i + 1 < NC) { CP_WAIT1(); } else { CP_WAIT0(); }
        __syncthreads();
        if (i + 2 < NC) { load_stage((i + 2) % 3, (i + 2) * 32); CP_COMMIT(); }
        compute_stage(sb + (i % 3) * STAGE_B, warp_m, warp_n, f, acc);
    }
    gemm_epilogue<BIAS, GATHER, PART>(acc, smem, tid, wid, lane, m0, n0, warp_m, warp_n, bias, C);
}

__global__ void __launch_bounds__(256, 1)
p2proj_kernel() {
    gemm_body<C2V, false, false, false>(g_p2h, g_p2l, g_w1bh, g_w1bl, nullptr, g_p2proj);
}
__global__ void __launch_bounds__(256, 1)
gemm1_kernel(const float* __restrict__ bias) {
    gemm_body<C1V, true, true, true>(g_p1h, g_p1l, g_w1ah, g_w1al, bias, g_h);
}

// ----- gemm2: fused BN1+ReLU+split A-loader (reads g_h fp32), 2-stage -----
__global__ void __launch_bounds__(256, 1)
gemm2_fused_kernel(const float* __restrict__ bias, float* __restrict__ C) {
    extern __shared__ char smem[];
    constexpr int K = OO, NC = K / 32;
    const uint32_t sb = smem_u32(smem);
    const int tid  = threadIdx.x;
    const int wid  = tid >> 5, lane = tid & 31;
    const int m0   = blockIdx.x << 7;
    const int n0   = blockIdx.y << 7;
    const int warp_m = (wid & 1) * 64;
    const int warp_n = (wid >> 1) * 32;

    // A loader mapping: row = tid>>1 (0..127), k-half = (tid&1)*16
    const int lr2 = tid >> 1;
    const int kh  = (tid & 1) * 16;
    const float* hrow = g_h + (size_t)(m0 + lr2) * K + kh;
    const uint32_t a_sts = (uint32_t)(lr2 * ROWP + kh * 2);

    // W loader (cp.async), same as generic
    const int lr = tid >> 2, lkg = tid & 3;
    const uint32_t l_dst = (uint32_t)(lr * ROWP + lkg * 16);
    const size_t   w_src0 = (size_t)(n0 + lr) * K + lkg * 8;
    const FragIdx f = frag_idx(lane);

    float acc[4][4][4];
    #pragma unroll
    for (int tm = 0; tm < 4; tm++)
        #pragma unroll
        for (int tn = 0; tn < 4; tn++)
            #pragma unroll
            for (int q = 0; q < 4; q++) acc[tm][tn][q] = 0.f;

    float4 Ar[4];   // one stage of A in regs (16 fp32)

    auto ldg_A = [&](int kc) {
        #pragma unroll
        for (int j = 0; j < 4; j++) Ar[j] = *(const float4*)(hrow + kc + j * 4);
    };
    // bnrelu + split + STS of Ar into stage s (channels kc+kh+0..15)
    auto sts_A = [&](int s, int kc) {
        const uint32_t base = sb + s * STAGE_B;
        #pragma unroll
        for (int j = 0; j < 4; j++) {
            const int c = kc + kh + j * 4;
            const float4 sc = *(const float4*)(g_s1 + c);
            const float4 sh = *(const float4*)(g_t1 + c);
            float4 v = Ar[j];
            v.x = fmaxf(fmaf(v.x, sc.x, sh.x), 0.f);
            v.y = fmaxf(fmaf(v.y, sc.y, sh.y), 0.f);
            v.z = fmaxf(fmaf(v.z, sc.z, sh.z), 0.f);
            v.w = fmaxf(fmaf(v.w, sc.w, sh.w), 0.f);
            union { __nv_bfloat16 bv[4]; uint32_t u[2]; } H, L;
            split_bf(v.x, H.bv[0], L.bv[0]);
            split_bf(v.y, H.bv[1], L.bv[1]);
            split_bf(v.z, H.bv[2], L.bv[2]);
            split_bf(v.w, H.bv[3], L.bv[3]);
            const uint32_t d = base + a_sts + j * 8;
            STS64(d,          H.u[0], H.u[1]);
            STS64(d + TILE_B, L.u[0], L.u[1]);
        }
    };
    auto load_W = [&](int s, int kc) {
        const uint32_t base = sb + s * STAGE_B;
        #pragma unroll
        for (int it = 0; it < 2; it++) {
            const uint32_t d = base + 2 * TILE_B + l_dst + it * (64 * ROWP);
            const size_t   wo = w_src0 + (size_t)(it * 64) * K + kc;
            cp_async16(d,          g_w2h + wo);
            cp_async16(d + TILE_B, g_w2l + wo);
        }
    };

    // prologue: stage 0 fully, prefetch A(1) to regs
    ldg_A(0);
    sts_A(0, 0);
    load_W(0, 0); CP_COMMIT();
    ldg_A(32);
    CP_WAIT0();
    __syncthreads();

    for (int i = 0; i < NC; i++) {
        if (i + 1 < NC) {
            sts_A((i + 1) & 1, (i + 1) * 32);       // Ar holds A(i+1)
            load_W((i + 1) & 1, (i + 1) * 32); CP_COMMIT();
            if (i + 2 < NC) ldg_A((i + 2) * 32);    // prefetch next into regs
        }
        compute_stage(sb + (i & 1) * STAGE_B, warp_m, warp_n, f, acc);
        if (i + 1 < NC) { CP_WAIT0(); __syncthreads(); }
    }
    gemm_epilogue<true, false, true>(acc, smem, tid, wid, lane, m0, n0, warp_m, warp_n, bias, C);
}

// ======================================================================
// BN finalize over 1024 m-block partials; 32 blocks x 8 warps
// ======================================================================
__global__ void bn_finalize_kernel(const float* __restrict__ g,
                                   const float* __restrict__ be, int which) {
    const int w = threadIdx.x >> 5, l = threadIdx.x & 31;
    const int c = blockIdx.x * 8 + w;
    float s = 0.f, ss = 0.f;
    for (int b = l; b < 1024; b += 32) {
        s  += g_part[(size_t)b * 512 + c];
        ss += g_part[(size_t)b * 512 + 256 + c];
    }
    #pragma unroll
    for (int o = 16; o; o >>= 1) {
        s  += __shfl_xor_sync(0xFFFFFFFFu, s, o);
        ss += __shfl_xor_sync(0xFFFFFFFFu, ss, o);
    }
    if (l == 0) {
        const float mu  = s * (1.0f / (float)MM);
        const float var = ss * (1.0f / (float)MM) - mu * mu;
        const float inv = rsqrtf(var + 1e-5f);
        const float sc  = g[c] * inv;
        const float sh  = be[c] - mu * sc;
        if (which) { g_s2[c] = sc; g_t2[c] = sh; }
        else       { g_s1[c] = sc; g_t1[c] = sh; }
    }
}

// Final: out = relu(out*scale2 + shift2) in place
__global__ void bn_relu_kernel(float* __restrict__ X) {
    const size_t i = (size_t)blockIdx.x * 256 + threadIdx.x;
    float4 v = ((float4*)X)[i];
    const int c4 = (int)(i & 63);
    const float4 sc = ((const float4*)g_s2)[c4];
    const float4 sh = ((const float4*)g_t2)[c4];
    v.x = fmaxf(fmaf(v.x, sc.x, sh.x), 0.f);
    v.y = fmaxf(fmaf(v.y, sc.y, sh.y), 0.f);
    v.z = fmaxf(fmaf(v.z, sc.z, sh.z), 0.f);
    v.w = fmaxf(fmaf(v.w, sc.w, sh.w), 0.f);
    ((float4*)X)[i] = v;
}

// ======================================================================
extern "C" void kernel_launch(void* const* d_in, const int* in_sizes, int n_in,
                              void* d_out, int out_size) {
    const float* xyz1    = (const float*)d_in[0];
    const float* xyz2    = (const float*)d_in[1];
    const float* points1 = (const float*)d_in[2];
    const float* points2 = (const float*)d_in[3];
    const float* W1      = (const float*)d_in[4];
    const float* b1      = (const float*)d_in[5];
    const float* g1      = (const float*)d_in[6];
    const float* be1     = (const float*)d_in[7];
    const float* W2      = (const float*)d_in[8];
    const float* b2      = (const float*)d_in[9];
    const float* g2      = (const float*)d_in[10];
    const float* be2     = (const float*)d_in[11];
    float* out = (float*)d_out;

    cudaFuncSetAttribute(p2proj_kernel,     cudaFuncAttributeMaxDynamicSharedMemorySize, GSMEM);
    cudaFuncSetAttribute(gemm1_kernel,      cudaFuncAttributeMaxDynamicSharedMemorySize, GSMEM);
    cudaFuncSetAttribute(gemm2_fused_kernel,cudaFuncAttributeMaxDynamicSharedMemorySize, GSMEM2);

    wconvert_kernel<<<(OO * CF + 255) / 256, 256>>>(W1, W2);
    p2convert_kernel<<<(P2R * C2V / 4) / 256, 256>>>(points2);
    knn_kernel<<<dim3(NN / 256, BB), 256>>>(xyz1, xyz2, points1);

    p2proj_kernel<<<dim3(P2R / 128, OO / 128), 256, GSMEM>>>();
    gemm1_kernel<<<dim3(MM / 128, OO / 128), 256, GSMEM>>>(b1);
    bn_finalize_kernel<<<32, 256>>>(g1, be1, 0);

    gemm2_fused_kernel<<<dim3(MM / 128, OO / 128), 256, GSMEM2>>>(b2, out);
    bn_finalize_kernel<<<32, 256>>>(g2, be2, 1);
    bn_relu_kernel<<<(MM * OO / 4) / 256, 256>>>(out);
}

// round 9
// speedup vs baseline: 2.1397x; 1.0282x over previous
#include <cuda_runtime.h>
#include <cuda_bf16.h>
#include <cstdint>
#include <math.h>

// Problem constants
#define BB 8
#define NN 16384
#define SSZ 2048
#define C1V 128
#define C2V 256
#define CF 384
#define MM (BB*NN)      /* 131072 rows */
#define OO 256          /* output channels per layer */
#define P2R (BB*SSZ)    /* 16384 points2 rows */

// -------- scratch (static device globals; ~237MB) --------
__device__ __align__(16) __nv_bfloat16 g_p1h[(size_t)MM * C1V];    // 33.5MB
__device__ __align__(16) __nv_bfloat16 g_p1l[(size_t)MM * C1V];    // 33.5MB
__device__ __align__(16) float         g_h[(size_t)MM * OO];       // 134MB pre-BN h
__device__ __align__(16) float         g_p2proj[(size_t)P2R * OO]; // 16.8MB
__device__ __align__(16) __nv_bfloat16 g_p2h[(size_t)P2R * C2V];   // 8.4MB
__device__ __align__(16) __nv_bfloat16 g_p2l[(size_t)P2R * C2V];   // 8.4MB
__device__ __align__(16) float         g_knn[(size_t)MM * 8];      // 4MB idx+w
__device__ __align__(16) __nv_bfloat16 g_w1ah[OO * C1V], g_w1al[OO * C1V];
__device__ __align__(16) __nv_bfloat16 g_w1bh[OO * C2V], g_w1bl[OO * C2V];
__device__ __align__(16) __nv_bfloat16 g_w2h[OO * OO],  g_w2l[OO * OO];
__device__ __align__(16) float g_part[1024 * 512];                 // 2MB
__device__ __align__(16) float g_s1[OO], g_t1[OO], g_s2[OO], g_t2[OO];

// ======================================================================
// helpers (NO 'a'-suffix features)
// ======================================================================
__device__ __forceinline__ uint32_t smem_u32(const void* p) {
    uint32_t a;
    asm("{ .reg .u64 t; cvta.to.shared.u64 t, %1; cvt.u32.u64 %0, t; }" : "=r"(a) : "l"(p));
    return a;
}
__device__ __forceinline__ void cp_async16(uint32_t dst, const void* src) {
    asm volatile("cp.async.cg.shared.global [%0], [%1], 16;" :: "r"(dst), "l"(src));
}
#define CP_COMMIT() asm volatile("cp.async.commit_group;" ::: "memory")
#define CP_WAIT1()  asm volatile("cp.async.wait_group 1;" ::: "memory")
#define CP_WAIT0()  asm volatile("cp.async.wait_group 0;" ::: "memory")

#define LDSM4(r0, r1, r2, r3, addr) \
    asm volatile("ldmatrix.sync.aligned.m8n8.x4.shared.b16 {%0,%1,%2,%3}, [%4];" \
                 : "=r"(r0), "=r"(r1), "=r"(r2), "=r"(r3) : "r"(addr))

#define STS128(addr, v0, v1, v2, v3) \
    asm volatile("st.shared.v4.b32 [%0], {%1,%2,%3,%4};" \
                 :: "r"(addr), "r"(v0), "r"(v1), "r"(v2), "r"(v3))

__device__ __forceinline__ void mma_bf16(float* c, const uint32_t* a, const uint32_t* b) {
    asm volatile("mma.sync.aligned.m16n8k16.row.col.f32.bf16.bf16.f32 "
                 "{%0,%1,%2,%3}, {%4,%5,%6,%7}, {%8,%9}, {%0,%1,%2,%3};"
                 : "+f"(c[0]), "+f"(c[1]), "+f"(c[2]), "+f"(c[3])
                 : "r"(a[0]), "r"(a[1]), "r"(a[2]), "r"(a[3]), "r"(b[0]), "r"(b[1]));
}

__device__ __forceinline__ void split_bf(float v, __nv_bfloat16& h, __nv_bfloat16& l) {
    h = __float2bfloat16_rn(v);
    l = __float2bfloat16_rn(v - __bfloat162float(h));
}

// ======================================================================
// Kernel 1: 3-NN search -> idx/weights; also converts points1 to bf16 split
// ======================================================================
__global__ void knn_kernel(const float* __restrict__ xyz1,
                           const float* __restrict__ xyz2,
                           const float* __restrict__ points1) {
    __shared__ float4 s4[SSZ];

    const int tid = threadIdx.x;
    const int b   = blockIdx.y;
    const int n0  = blockIdx.x * 256;

    const float* x2 = xyz2 + (size_t)b * SSZ * 3;
    for (int s = tid; s < SSZ; s += 256) {
        s4[s] = make_float4(x2[3*s], x2[3*s+1], x2[3*s+2], 0.f);
    }
    __syncthreads();

    const int n = n0 + tid;
    const float* p = xyz1 + ((size_t)b * NN + n) * 3;
    const float px = p[0], py = p[1], pz = p[2];
    float b0 = 3.4e38f, b1 = 3.4e38f, b2 = 3.4e38f;
    int   j0 = 0, j1 = 0, j2 = 0;
    #pragma unroll 4
    for (int s = 0; s < SSZ; ++s) {
        float4 q = s4[s];
        float dx = px - q.x, dy = py - q.y, dz = pz - q.z;
        float d = dx*dx + dy*dy + dz*dz;
        if (d < b2) {
            if (d < b1) {
                b2 = b1; j2 = j1;
                if (d < b0) { b1 = b0; j1 = j0; b0 = d; j0 = s; }
                else        { b1 = d;  j1 = s; }
            } else { b2 = d; j2 = s; }
        }
    }
    float r0 = 1.f / (sqrtf(b0) + 1e-8f);
    float r1 = 1.f / (sqrtf(b1) + 1e-8f);
    float r2 = 1.f / (sqrtf(b2) + 1e-8f);
    float rs = 1.f / (r0 + r1 + r2);

    const size_t row = (size_t)b * NN + n;
    float4 ia, wa;
    ia.x = __int_as_float(b * SSZ + j0);
    ia.y = __int_as_float(b * SSZ + j1);
    ia.z = __int_as_float(b * SSZ + j2);
    ia.w = 0.f;
    wa.x = r0 * rs; wa.y = r1 * rs; wa.z = r2 * rs; wa.w = 0.f;
    ((float4*)g_knn)[row * 2]     = ia;
    ((float4*)g_knn)[row * 2 + 1] = wa;

    // points1 -> bf16 split
    const float4* p1 = (const float4*)(points1 + ((size_t)b * NN + n0) * C1V);
    for (int i = tid; i < 256 * 32; i += 256) {
        float4 v = p1[i];
        union { __nv_bfloat16 bv[4]; uint2 u; } H, L;
        split_bf(v.x, H.bv[0], L.bv[0]);
        split_bf(v.y, H.bv[1], L.bv[1]);
        split_bf(v.z, H.bv[2], L.bv[2]);
        split_bf(v.w, H.bv[3], L.bv[3]);
        const size_t off4 = ((size_t)b * NN + n0) * 32 + i;
        ((uint2*)g_p1h)[off4] = H.u;
        ((uint2*)g_p1l)[off4] = L.u;
    }
}

// ======================================================================
// converts: weights W1 (split into a/b parts) + W2; points2
// ======================================================================
__global__ void wconvert_kernel(const float* __restrict__ W1,
                                const float* __restrict__ W2) {
    int i = blockIdx.x * 256 + threadIdx.x;
    if (i < OO * CF) {
        int o = i / CF, c = i - o * CF;
        __nv_bfloat16 h, l; split_bf(W1[i], h, l);
        if (c < C1V) { g_w1ah[o * C1V + c] = h; g_w1al[o * C1V + c] = l; }
        else         { g_w1bh[o * C2V + c - C1V] = h; g_w1bl[o * C2V + c - C1V] = l; }
    }
    if (i < OO * OO) { __nv_bfloat16 h, l; split_bf(W2[i], h, l); g_w2h[i] = h; g_w2l[i] = l; }
}

__global__ void p2convert_kernel(const float* __restrict__ points2) {
    const size_t i = (size_t)blockIdx.x * 256 + threadIdx.x;
    float4 v = ((const float4*)points2)[i];
    union { __nv_bfloat16 bv[4]; uint2 u; } H, L;
    split_bf(v.x, H.bv[0], L.bv[0]);
    split_bf(v.y, H.bv[1], L.bv[1]);
    split_bf(v.z, H.bv[2], L.bv[2]);
    split_bf(v.w, H.bv[3], L.bv[3]);
    ((uint2*)g_p2h)[i] = H.u;
    ((uint2*)g_p2l)[i] = L.u;
}

// ======================================================================
// GEMM core: CTA 128x128, 512 threads / 16 warps (4m x 4n), warp 32x32.
// 4 warps per SMSP for latency hiding (was 2 -> tensor util ~37%).
// smem stage: Ah[128xROWP] | Al | Wh | Wl
// ======================================================================
#define ROWP 80
#define TILE_B (128 * ROWP)
#define STAGE_B (4 * TILE_B)
#define GSMEM   (3 * STAGE_B)
#define GSMEM2  (2 * STAGE_B)
#define NTHR 512

struct FragIdx { uint32_t a_off, b_off; };
__device__ __forceinline__ FragIdx frag_idx(int lane) {
    const int g = lane >> 3, l7 = lane & 7;
    FragIdx f;
    f.a_off = (uint32_t)((l7 + (g & 1) * 8) * ROWP + (g >> 1) * 16);
    f.b_off = (uint32_t)(((g >> 1) * 8 + l7) * ROWP + (g & 1) * 16);
    return f;
}

// one K-chunk (32) of MMA compute; warp tile 32x32: acc[2][4][4]
__device__ __forceinline__ void compute_stage(uint32_t base, int warp_m, int warp_n,
                                              const FragIdx& f, float acc[2][4][4]) {
    #pragma unroll
    for (int ks = 0; ks < 2; ks++) {
        uint32_t ah[2][4], al[2][4], w[4][2];
        #pragma unroll
        for (int tm = 0; tm < 2; tm++) {
            const uint32_t ad = base + f.a_off + (uint32_t)((warp_m + tm * 16) * ROWP + ks * 32);
            LDSM4(ah[tm][0], ah[tm][1], ah[tm][2], ah[tm][3], ad);
            LDSM4(al[tm][0], al[tm][1], al[tm][2], al[tm][3], ad + TILE_B);
        }
        #pragma unroll
        for (int tp = 0; tp < 2; tp++) {
            const uint32_t bd = base + 2 * TILE_B + f.b_off
                              + (uint32_t)((warp_n + tp * 16) * ROWP + ks * 32);
            LDSM4(w[2*tp][0], w[2*tp][1], w[2*tp+1][0], w[2*tp+1][1], bd);
        }
        #pragma unroll
        for (int tm = 0; tm < 2; tm++)
            #pragma unroll
            for (int tn = 0; tn < 4; tn++) mma_bf16(acc[tm][tn], ah[tm], w[tn]);
        #pragma unroll
        for (int tm = 0; tm < 2; tm++)
            #pragma unroll
            for (int tn = 0; tn < 4; tn++) mma_bf16(acc[tm][tn], al[tm], w[tn]);
        #pragma unroll
        for (int tp = 0; tp < 2; tp++) {
            const uint32_t bd = base + 3 * TILE_B + f.b_off
                              + (uint32_t)((warp_n + tp * 16) * ROWP + ks * 32);
            LDSM4(w[2*tp][0], w[2*tp][1], w[2*tp+1][0], w[2*tp+1][1], bd);
        }
        #pragma unroll
        for (int tm = 0; tm < 2; tm++)
            #pragma unroll
            for (int tn = 0; tn < 4; tn++) mma_bf16(acc[tm][tn], ah[tm], w[tn]);
    }
}

// epilogue: optional bias, gather, BN-partials, then store
template<bool BIAS, bool GATHER, bool PART>
__device__ __forceinline__ void gemm_epilogue(float acc[2][4][4], char* smem,
                                              int tid, int wid, int lane,
                                              int m0, int n0, int warp_m, int warp_n,
                                              const float* bias, float* C) {
    if (BIAS) {
        #pragma unroll
        for (int tn = 0; tn < 4; tn++) {
            float2 bv = *(const float2*)(bias + n0 + warp_n + tn * 8 + (lane & 3) * 2);
            #pragma unroll
            for (int tm = 0; tm < 2; tm++) {
                acc[tm][tn][0] += bv.x; acc[tm][tn][1] += bv.y;
                acc[tm][tn][2] += bv.x; acc[tm][tn][3] += bv.y;
            }
        }
    }
    if (GATHER) {
        #pragma unroll
        for (int tm = 0; tm < 2; tm++) {
            const int r_lo = m0 + warp_m + tm * 16 + (lane >> 2);
            const int r_hi = r_lo + 8;
            float4 ia = ((const float4*)g_knn)[(size_t)r_lo * 2];
            float4 wa = ((const float4*)g_knn)[(size_t)r_lo * 2 + 1];
            float4 ib = ((const float4*)g_knn)[(size_t)r_hi * 2];
            float4 wb = ((const float4*)g_knn)[(size_t)r_hi * 2 + 1];
            const int   gl[3] = { __float_as_int(ia.x), __float_as_int(ia.y), __float_as_int(ia.z) };
            const float wl[3] = { wa.x, wa.y, wa.z };
            const int   gh[3] = { __float_as_int(ib.x), __float_as_int(ib.y), __float_as_int(ib.z) };
            const float wh[3] = { wb.x, wb.y, wb.z };
            #pragma unroll
            for (int k = 0; k < 3; k++) {
                const float* pl = g_p2proj + (size_t)gl[k] * OO + n0;
                const float* ph = g_p2proj + (size_t)gh[k] * OO + n0;
                #pragma unroll
                for (int tn = 0; tn < 4; tn++) {
                    const int col = warp_n + tn * 8 + (lane & 3) * 2;
                    float2 vl = *(const float2*)(pl + col);
                    float2 vh = *(const float2*)(ph + col);
                    acc[tm][tn][0] += wl[k] * vl.x; acc[tm][tn][1] += wl[k] * vl.y;
                    acc[tm][tn][2] += wh[k] * vh.x; acc[tm][tn][3] += wh[k] * vh.y;
                }
            }
        }
    }
    if (PART) {
        __syncthreads();
        float* sP  = (float*)smem;        // [4][128]
        float* ssP = sP + 512;            // [4][128]
        const int mg = wid & 3;
        #pragma unroll
        for (int tn = 0; tn < 4; tn++) {
            #pragma unroll
            for (int p = 0; p < 2; p++) {
                float s = 0.f, ss = 0.f;
                #pragma unroll
                for (int tm = 0; tm < 2; tm++) {
                    float a = acc[tm][tn][p], b = acc[tm][tn][2 + p];
                    s += a + b; ss += a * a + b * b;
                }
                #pragma unroll
                for (int o = 4; o <= 16; o <<= 1) {
                    s  += __shfl_xor_sync(0xFFFFFFFFu, s, o);
                    ss += __shfl_xor_sync(0xFFFFFFFFu, ss, o);
                }
                if (lane < 4) {
                    const int cl = warp_n + tn * 8 + (lane & 3) * 2 + p;
                    sP [mg * 128 + cl] = s;
                    ssP[mg * 128 + cl] = ss;
                }
            }
        }
        __syncthreads();
        if (tid < 128) {
            const float s  = sP[tid]  + sP[128 + tid]  + sP[256 + tid]  + sP[384 + tid];
            const float ss = ssP[tid] + ssP[128 + tid] + ssP[256 + tid] + ssP[384 + tid];
            g_part[(size_t)blockIdx.x * 512 + n0 + tid]       = s;
            g_part[(size_t)blockIdx.x * 512 + 256 + n0 + tid] = ss;
        }
    }
    #pragma unroll
    for (int tm = 0; tm < 2; tm++) {
        const int r0 = m0 + warp_m + tm * 16 + (lane >> 2);
        float* c0 = C + (size_t)r0 * OO + n0;
        #pragma unroll
        for (int tn = 0; tn < 4; tn++) {
            const int col = warp_n + tn * 8 + (lane & 3) * 2;
            *(float2*)(c0 + col)          = make_float2(acc[tm][tn][0], acc[tm][tn][1]);
            *(float2*)(c0 + 8 * OO + col) = make_float2(acc[tm][tn][2], acc[tm][tn][3]);
        }
    }
}

// ----- generic bf16-split GEMM (cp.async A and W), 3-stage, 512 threads -----
template<int K, bool BIAS, bool GATHER, bool PART>
__device__ __forceinline__ void gemm_body(const __nv_bfloat16* __restrict__ Ah,
                                          const __nv_bfloat16* __restrict__ Al,
                                          const __nv_bfloat16* __restrict__ Wh,
                                          const __nv_bfloat16* __restrict__ Wl,
                                          const float* __restrict__ bias,
                                          float* __restrict__ C) {
    extern __shared__ char smem[];
    constexpr int NC = K / 32;
    const uint32_t sb = smem_u32(smem);
    const int tid  = threadIdx.x;
    const int wid  = tid >> 5, lane = tid & 31;
    const int m0   = blockIdx.x << 7;
    const int n0   = blockIdx.y << 7;
    const int warp_m = (wid & 3) * 32;
    const int warp_n = (wid >> 2) * 32;

    // loaders: 512 threads, 128 rows x 4 16B-chunks each buffer
    const int lr = tid >> 2, lkg = tid & 3;
    const uint32_t l_dst = (uint32_t)(lr * ROWP + lkg * 16);
    const size_t   a_src0 = (size_t)(m0 + lr) * K + lkg * 8;
    const size_t   w_src0 = (size_t)(n0 + lr) * K + lkg * 8;
    const FragIdx f = frag_idx(lane);

    float acc[2][4][4];
    #pragma unroll
    for (int tm = 0; tm < 2; tm++)
        #pragma unroll
        for (int tn = 0; tn < 4; tn++)
            #pragma unroll
            for (int q = 0; q < 4; q++) acc[tm][tn][q] = 0.f;

    auto load_stage = [&](int s, int kc) {
        const uint32_t base = sb + s * STAGE_B;
        cp_async16(base + l_dst,              Ah + a_src0 + kc);
        cp_async16(base + l_dst + TILE_B,     Al + a_src0 + kc);
        cp_async16(base + l_dst + 2 * TILE_B, Wh + w_src0 + kc);
        cp_async16(base + l_dst + 3 * TILE_B, Wl + w_src0 + kc);
    };

    load_stage(0, 0);  CP_COMMIT();
    load_stage(1, 32); CP_COMMIT();

    for (int i = 0; i < NC; i++) {
        if (i + 1 < NC) { CP_WAIT1(); } else { CP_WAIT0(); }
        __syncthreads();
        if (i + 2 < NC) { load_stage((i + 2) % 3, (i + 2) * 32); CP_COMMIT(); }
        compute_stage(sb + (i % 3) * STAGE_B, warp_m, warp_n, f, acc);
    }
    gemm_epilogue<BIAS, GATHER, PART>(acc, smem, tid, wid, lane, m0, n0, warp_m, warp_n, bias, C);
}

__global__ void __launch_bounds__(NTHR, 1)
p2proj_kernel() {
    gemm_body<C2V, false, false, false>(g_p2h, g_p2l, g_w1bh, g_w1bl, nullptr, g_p2proj);
}
__global__ void __launch_bounds__(NTHR, 1)
gemm1_kernel(const float* __restrict__ bias) {
    gemm_body<C1V, true, true, true>(g_p1h, g_p1l, g_w1ah, g_w1al, bias, g_h);
}

// ----- gemm2: fused BN1+ReLU+split A-loader (reads g_h fp32), 2-stage -----
__global__ void __launch_bounds__(NTHR, 1)
gemm2_fused_kernel(const float* __restrict__ bias, float* __restrict__ C) {
    extern __shared__ char smem[];
    constexpr int K = OO, NC = K / 32;
    const uint32_t sb = smem_u32(smem);
    const int tid  = threadIdx.x;
    const int wid  = tid >> 5, lane = tid & 31;
    const int m0   = blockIdx.x << 7;
    const int n0   = blockIdx.y << 7;
    const int warp_m = (wid & 3) * 32;
    const int warp_n = (wid >> 2) * 32;

    // A loader: row = tid>>2, quad = tid&3 -> 8 fp32 cols per thread per stage
    const int lr = tid >> 2, quad = tid & 3;
    const float* hrow = g_h + (size_t)(m0 + lr) * K + quad * 8;
    const uint32_t a_sts = (uint32_t)(lr * ROWP + quad * 16);
    const size_t   w_src0 = (size_t)(n0 + lr) * K + quad * 8;
    const uint32_t l_dst = (uint32_t)(lr * ROWP + quad * 16);
    const FragIdx f = frag_idx(lane);

    float acc[2][4][4];
    #pragma unroll
    for (int tm = 0; tm < 2; tm++)
        #pragma unroll
        for (int tn = 0; tn < 4; tn++)
            #pragma unroll
            for (int q = 0; q < 4; q++) acc[tm][tn][q] = 0.f;

    float4 Ar[2];

    auto ldg_A = [&](int kc) {
        Ar[0] = *(const float4*)(hrow + kc);
        Ar[1] = *(const float4*)(hrow + kc + 4);
    };
    auto sts_A = [&](int s, int kc) {
        const uint32_t base = sb + s * STAGE_B;
        const int c = kc + quad * 8;
        union { __nv_bfloat16 bv[8]; uint32_t u[4]; } H, L;
        #pragma unroll
        for (int j = 0; j < 2; j++) {
            const float4 sc = *(const float4*)(g_s1 + c + j * 4);
            const float4 sh = *(const float4*)(g_t1 + c + j * 4);
            float4 v = Ar[j];
            v.x = fmaxf(fmaf(v.x, sc.x, sh.x), 0.f);
            v.y = fmaxf(fmaf(v.y, sc.y, sh.y), 0.f);
            v.z = fmaxf(fmaf(v.z, sc.z, sh.z), 0.f);
            v.w = fmaxf(fmaf(v.w, sc.w, sh.w), 0.f);
            split_bf(v.x, H.bv[j*4+0], L.bv[j*4+0]);
            split_bf(v.y, H.bv[j*4+1], L.bv[j*4+1]);
            split_bf(v.z, H.bv[j*4+2], L.bv[j*4+2]);
            split_bf(v.w, H.bv[j*4+3], L.bv[j*4+3]);
        }
        STS128(base + a_sts,          H.u[0], H.u[1], H.u[2], H.u[3]);
        STS128(base + a_sts + TILE_B, L.u[0], L.u[1], L.u[2], L.u[3]);
    };
    auto load_W = [&](int s, int kc) {
        const uint32_t base = sb + s * STAGE_B;
        cp_async16(base + 2 * TILE_B + l_dst, g_w2h + w_src0 + kc);
        cp_async16(base + 3 * TILE_B + l_dst, g_w2l + w_src0 + kc);
    };

    ldg_A(0);
    sts_A(0, 0);
    load_W(0, 0); CP_COMMIT();
    ldg_A(32);
    CP_WAIT0();
    __syncthreads();

    for (int i = 0; i < NC; i++) {
        if (i + 1 < NC) {
            sts_A((i + 1) & 1, (i + 1) * 32);
            load_W((i + 1) & 1, (i + 1) * 32); CP_COMMIT();
            if (i + 2 < NC) ldg_A((i + 2) * 32);
        }
        compute_stage(sb + (i & 1) * STAGE_B, warp_m, warp_n, f, acc);
        if (i + 1 < NC) { CP_WAIT0(); __syncthreads(); }
    }
    gemm_epilogue<true, false, true>(acc, smem, tid, wid, lane, m0, n0, warp_m, warp_n, bias, C);
}

// ======================================================================
// BN finalize over 1024 m-block partials; 32 blocks x 8 warps
// ======================================================================
__global__ void bn_finalize_kernel(const float* __restrict__ g,
                                   const float* __restrict__ be, int which) {
    const int w = threadIdx.x >> 5, l = threadIdx.x & 31;
    const int c = blockIdx.x * 8 + w;
    float s = 0.f, ss = 0.f;
    for (int b = l; b < 1024; b += 32) {
        s  += g_part[(size_t)b * 512 + c];
        ss += g_part[(size_t)b * 512 + 256 + c];
    }
    #pragma unroll
    for (int o = 16; o; o >>= 1) {
        s  += __shfl_xor_sync(0xFFFFFFFFu, s, o);
        ss += __shfl_xor_sync(0xFFFFFFFFu, ss, o);
    }
    if (l == 0) {
        const float mu  = s * (1.0f / (float)MM);
        const float var = ss * (1.0f / (float)MM) - mu * mu;
        const float inv = rsqrtf(var + 1e-5f);
        const float sc  = g[c] * inv;
        const float sh  = be[c] - mu * sc;
        if (which) { g_s2[c] = sc; g_t2[c] = sh; }
        else       { g_s1[c] = sc; g_t1[c] = sh; }
    }
}

// Final: out = relu(out*scale2 + shift2) in place
__global__ void bn_relu_kernel(float* __restrict__ X) {
    const size_t i = (size_t)blockIdx.x * 256 + threadIdx.x;
    float4 v = ((float4*)X)[i];
    const int c4 = (int)(i & 63);
    const float4 sc = ((const float4*)g_s2)[c4];
    const float4 sh = ((const float4*)g_t2)[c4];
    v.x = fmaxf(fmaf(v.x, sc.x, sh.x), 0.f);
    v.y = fmaxf(fmaf(v.y, sc.y, sh.y), 0.f);
    v.z = fmaxf(fmaf(v.z, sc.z, sh.z), 0.f);
    v.w = fmaxf(fmaf(v.w, sc.w, sh.w), 0.f);
    ((float4*)X)[i] = v;
}

// ======================================================================
extern "C" void kernel_launch(void* const* d_in, const int* in_sizes, int n_in,
                              void* d_out, int out_size) {
    const float* xyz1    = (const float*)d_in[0];
    const float* xyz2    = (const float*)d_in[1];
    const float* points1 = (const float*)d_in[2];
    const float* points2 = (const float*)d_in[3];
    const float* W1      = (const float*)d_in[4];
    const float* b1      = (const float*)d_in[5];
    const float* g1      = (const float*)d_in[6];
    const float* be1     = (const float*)d_in[7];
    const float* W2      = (const float*)d_in[8];
    const float* b2      = (const float*)d_in[9];
    const float* g2      = (const float*)d_in[10];
    const float* be2     = (const float*)d_in[11];
    float* out = (float*)d_out;

    cudaFuncSetAttribute(p2proj_kernel,      cudaFuncAttributeMaxDynamicSharedMemorySize, GSMEM);
    cudaFuncSetAttribute(gemm1_kernel,       cudaFuncAttributeMaxDynamicSharedMemorySize, GSMEM);
    cudaFuncSetAttribute(gemm2_fused_kernel, cudaFuncAttributeMaxDynamicSharedMemorySize, GSMEM2);

    wconvert_kernel<<<(OO * CF + 255) / 256, 256>>>(W1, W2);
    p2convert_kernel<<<(P2R * C2V / 4) / 256, 256>>>(points2);
    knn_kernel<<<dim3(NN / 256, BB), 256>>>(xyz1, xyz2, points1);

    p2proj_kernel<<<dim3(P2R / 128, OO / 128), NTHR, GSMEM>>>();
    gemm1_kernel<<<dim3(MM / 128, OO / 128), NTHR, GSMEM>>>(b1);
    bn_finalize_kernel<<<32, 256>>>(g1, be1, 0);

    gemm2_fused_kernel<<<dim3(MM / 128, OO / 128), NTHR, GSMEM2>>>(b2, out);
    bn_finalize_kernel<<<32, 256>>>(g2, be2, 1);
    bn_relu_kernel<<<(MM * OO / 4) / 256, 256>>>(out);
}